// round 3
// baseline (speedup 1.0000x reference)
#include <cuda_runtime.h>
#include <math.h>

#define Nn 16384
#define Ee 262144
#define Tt 4
#define Dd 64
#define Ll 2
#define TND (Tt*Nn*Dd)

// ---- scratch (static __device__, allocation-free) ----
__device__ int   g_rowr[Ee], g_colr[Ee], g_etr[Ee];
__device__ int   g_scol[Ee], g_set[Ee];
__device__ int   g_deg[Nn], g_off[Nn + 1], g_cur[Nn];
__device__ int   g_bsum[16], g_bbase[16];
__device__ float g_h[TND];
__device__ float g_hw[TND];
__device__ float g_si[Tt * Nn], g_sj[Tt * Nn];
__device__ float g_p[Tt * Ee];
__device__ float g_den[Tt * Nn];
__device__ float g_ef[Tt * Dd];
__device__ float g_rg[Tt * Tt];
__device__ float g_vg[Tt * Dd];
__device__ int   g_is64;

// ---- dtype detect (parallel): int64 data always in [0,N); int32-as-int64 is not ----
__global__ void k_detect(const void* eidx) {
    __shared__ int bad;
    if (threadIdx.x == 0) bad = 0;
    __syncthreads();
    const long long* p = (const long long*)eidx;
    int b = 0;
#pragma unroll
    for (int k = 0; k < 4; k++) {
        long long v = p[threadIdx.x + k * 256];
        if (v < 0 || v >= Nn) b = 1;
    }
    if (b) atomicExch(&bad, 1);
    __syncthreads();
    if (threadIdx.x == 0) g_is64 = !bad;
}

// ---- setup ----
__global__ void k_init(const float* __restrict__ x, const float* __restrict__ ef0) {
    int i = blockIdx.x * blockDim.x + threadIdx.x;
    int stride = gridDim.x * blockDim.x;
    for (int j = i; j < TND; j += stride) {
        int nd = j & (Nn * Dd - 1);
        g_h[j] = x[nd];
    }
    if (i < Tt * Dd) g_ef[i] = ef0[i];
    for (int j = i; j < Nn; j += stride) g_deg[j] = 0;
}

__global__ void k_hist(const void* __restrict__ eidx, const void* __restrict__ etyp) {
    int e = blockIdx.x * blockDim.x + threadIdx.x;
    if (e >= Ee) return;
    int r, c, t;
    if (g_is64) {
        r = (int)((const long long*)eidx)[e];
        c = (int)((const long long*)eidx)[Ee + e];
        t = (int)((const long long*)etyp)[e];
    } else {
        r = ((const int*)eidx)[e];
        c = ((const int*)eidx)[Ee + e];
        t = ((const int*)etyp)[e];
    }
    g_rowr[e] = r; g_colr[e] = c; g_etr[e] = t;
    atomicAdd(&g_deg[r], 1);
}

// ---- parallel 3-phase exclusive scan of degrees ----
__global__ void k_scanA() {
    __shared__ int sh[1024];
    int b = blockIdx.x, tid = threadIdx.x;
    int i = b * 1024 + tid;
    int v = g_deg[i];
    sh[tid] = v;
    __syncthreads();
    for (int off = 1; off < 1024; off <<= 1) {
        int u = (tid >= off) ? sh[tid - off] : 0;
        __syncthreads();
        sh[tid] += u;
        __syncthreads();
    }
    g_off[i] = sh[tid] - v;          // exclusive within block
    if (tid == 1023) g_bsum[b] = sh[tid];
}

__global__ void k_scanB() {
    int tid = threadIdx.x;           // 32 threads
    int v = (tid < 16) ? g_bsum[tid] : 0;
    int inc = v;
#pragma unroll
    for (int off = 1; off < 32; off <<= 1) {
        int u = __shfl_up_sync(0xffffffffu, inc, off);
        if (tid >= off) inc += u;
    }
    if (tid < 16) g_bbase[tid] = inc - v;
}

__global__ void k_scanC() {
    int b = blockIdx.x, tid = threadIdx.x;
    int i = b * 1024 + tid;
    int o = g_off[i] + g_bbase[b];
    g_off[i] = o;
    g_cur[i] = o;
    if (i == 0) g_off[Nn] = Ee;
}

__global__ void k_scatter() {
    int e = blockIdx.x * blockDim.x + threadIdx.x;
    if (e >= Ee) return;
    int pos = atomicAdd(&g_cur[g_rowr[e]], 1);
    g_scol[pos] = g_colr[e];
    g_set[pos]  = g_etr[e];
}

// ---- per-layer tiny math ----
__global__ void k_rgef(const float* __restrict__ theta, const float* __restrict__ wr, int layer) {
    __shared__ float ef_s[Tt * Dd];
    int tid = threadIdx.x;              // 256
    ef_s[tid] = g_ef[tid];
    __syncthreads();
    const float* th = theta + (size_t)layer * Tt * 3 * Dd;
    if (tid < Tt * Tt) {
        int t1 = tid >> 2, t2 = tid & 3;
        const float* tg = th + t1 * 3 * Dd;
        float s = 0.f;
#pragma unroll
        for (int k = 0; k < Dd; k++) s += tg[k] * ef_s[t2 * Dd + k];
        g_rg[tid] = s;
    }
    {
        int t = tid >> 6, d = tid & 63;
        const float* w = wr + (size_t)layer * Dd * Dd;
        float s = 0.f;
#pragma unroll
        for (int k = 0; k < Dd; k++) s += ef_s[t * Dd + k] * w[k * Dd + d];
        g_vg[tid] = 1.f / (1.f + __expf(-s));
        g_ef[tid] = (layer < Ll - 1) ? fmaxf(s, 0.f) : s;
    }
}

// ---- GEMM (h @ we) fused with si/sj dot products ----
__global__ void k_gemm(const float* __restrict__ we, const float* __restrict__ theta, int layer) {
    __shared__ float we_s[Dd * Dd];
    __shared__ float h_s[32 * Dd];
    __shared__ float thi_s[Dd], thj_s[Dd];
    int tid = threadIdx.x;              // 256
    int t = blockIdx.y;
    int n0 = blockIdx.x * 32;
    const float* w = we + (size_t)layer * Dd * Dd;
#pragma unroll
    for (int i = 0; i < 16; i++) we_s[tid + i * 256] = w[tid + i * 256];
    const float* hb = g_h + (size_t)t * Nn * Dd + (size_t)n0 * Dd;
#pragma unroll
    for (int i = 0; i < 8; i++) h_s[tid + i * 256] = hb[tid + i * 256];
    const float* th = theta + (size_t)layer * Tt * 3 * Dd + t * 3 * Dd;
    if (tid < Dd) thi_s[tid] = th[Dd + tid];
    else if (tid < 2 * Dd) thj_s[tid - Dd] = th[Dd + tid];   // th[2*Dd + (tid-Dd)]
    __syncthreads();
    int d = tid & 63, ng = tid >> 6;
    float acc[8] = {0.f, 0.f, 0.f, 0.f, 0.f, 0.f, 0.f, 0.f};
#pragma unroll
    for (int k = 0; k < Dd; k++) {
        float wv = we_s[k * Dd + d];
#pragma unroll
        for (int j = 0; j < 8; j++) acc[j] += h_s[(ng * 8 + j) * Dd + k] * wv;
    }
    float* ob = g_hw + (size_t)t * Nn * Dd + (size_t)n0 * Dd;
#pragma unroll
    for (int j = 0; j < 8; j++) ob[(ng * 8 + j) * Dd + d] = acc[j];

    // fused si/sj: 8 warps x 4 nodes
    int wid = tid >> 5, lane = tid & 31;
#pragma unroll
    for (int j = 0; j < 4; j++) {
        int nl = wid * 4 + j;
        float a = h_s[nl * Dd + lane], b = h_s[nl * Dd + lane + 32];
        float si = a * thi_s[lane] + b * thi_s[lane + 32];
        float sj = a * thj_s[lane] + b * thj_s[lane + 32];
#pragma unroll
        for (int o = 16; o; o >>= 1) {
            si += __shfl_down_sync(0xffffffffu, si, o);
            sj += __shfl_down_sync(0xffffffffu, sj, o);
        }
        if (lane == 0) {
            g_si[t * Nn + n0 + nl] = si;
            g_sj[t * Nn + n0 + nl] = sj;
        }
    }
}

// ---- scatter softmax: warp per node ----
__global__ void k_soft() {
    __shared__ float rg_s[Tt * Tt];
    if (threadIdx.x < Tt * Tt) rg_s[threadIdx.x] = g_rg[threadIdx.x];
    __syncthreads();
    int warp = threadIdx.x >> 5, lane = threadIdx.x & 31;
    int n = blockIdx.x * 4 + warp;
    int beg = g_off[n], end = g_off[n + 1];
    float siv[Tt];
#pragma unroll
    for (int t = 0; t < Tt; t++) siv[t] = g_si[t * Nn + n];
    float m[Tt] = {-3.4e38f, -3.4e38f, -3.4e38f, -3.4e38f};
    for (int e = beg + lane; e < end; e += 32) {
        int c = g_scol[e], ty = g_set[e];
#pragma unroll
        for (int t = 0; t < Tt; t++) {
            float l = rg_s[t * 4 + ty] + siv[t] + g_sj[t * Nn + c];
            m[t] = fmaxf(m[t], l);
        }
    }
#pragma unroll
    for (int t = 0; t < Tt; t++)
#pragma unroll
        for (int o = 16; o; o >>= 1) m[t] = fmaxf(m[t], __shfl_xor_sync(0xffffffffu, m[t], o));
    float s[Tt] = {0.f, 0.f, 0.f, 0.f};
    for (int e = beg + lane; e < end; e += 32) {
        int c = g_scol[e], ty = g_set[e];
#pragma unroll
        for (int t = 0; t < Tt; t++) {
            float l = rg_s[t * 4 + ty] + siv[t] + g_sj[t * Nn + c];
            float p = __expf(l - m[t]);
            s[t] += p;
            g_p[t * Ee + e] = p;
        }
    }
#pragma unroll
    for (int t = 0; t < Tt; t++)
#pragma unroll
        for (int o = 16; o; o >>= 1) s[t] += __shfl_xor_sync(0xffffffffu, s[t], o);
    if (lane == 0) {
#pragma unroll
        for (int t = 0; t < Tt; t++) g_den[t * Nn + n] = s[t];
    }
}

// ---- aggregation: block(256) per node, thread=(t,d), 4x unrolled edge loop ----
__global__ void k_agg(float* __restrict__ out, int final_layer, int dorelu) {
    __shared__ float vg_s[Tt * Dd];
    int tid = threadIdx.x;              // 256
    vg_s[tid] = g_vg[tid];
    __syncthreads();
    int t = tid >> 6, d = tid & 63;
    int n = blockIdx.x;
    int beg = g_off[n], end = g_off[n + 1];
    const float* hwb = g_hw + (size_t)t * (Nn * Dd) + d;
    const float* pb  = g_p + (size_t)t * Ee;
    const float* vgt = vg_s + d;
    float acc = 0.f;
    int e = beg;
    for (; e + 4 <= end; e += 4) {
        int c0 = g_scol[e],     c1 = g_scol[e + 1], c2 = g_scol[e + 2], c3 = g_scol[e + 3];
        int y0 = g_set[e],      y1 = g_set[e + 1],  y2 = g_set[e + 2],  y3 = g_set[e + 3];
        float p0 = pb[e],       p1 = pb[e + 1],     p2 = pb[e + 2],     p3 = pb[e + 3];
        float h0 = hwb[(size_t)c0 * Dd];
        float h1 = hwb[(size_t)c1 * Dd];
        float h2 = hwb[(size_t)c2 * Dd];
        float h3 = hwb[(size_t)c3 * Dd];
        acc += p0 * vgt[y0 * Dd] * h0;
        acc += p1 * vgt[y1 * Dd] * h1;
        acc += p2 * vgt[y2 * Dd] * h2;
        acc += p3 * vgt[y3 * Dd] * h3;
    }
    for (; e < end; e++) {
        int c = g_scol[e], y = g_set[e];
        acc += pb[e] * vgt[y * Dd] * hwb[(size_t)c * Dd];
    }
    float den = g_den[t * Nn + n];
    float inv = den > 0.f ? 1.f / den : 0.f;
    float v = acc * inv;
    if (dorelu) v = fmaxf(v, 0.f);
    float* dst = final_layer ? out : g_h;
    dst[(size_t)t * (Nn * Dd) + (size_t)n * Dd + d] = v;
}

extern "C" void kernel_launch(void* const* d_in, const int* in_sizes, int n_in,
                              void* d_out, int out_size) {
    const float* x     = (const float*)d_in[0];
    const float* ef0   = (const float*)d_in[1];
    const float* theta = (const float*)d_in[2];
    const float* wr    = (const float*)d_in[3];
    const float* we    = (const float*)d_in[4];
    const void*  eidx  = d_in[5];
    const void*  etyp  = d_in[6];
    float* out = (float*)d_out;

    k_detect<<<1, 256>>>(eidx);
    k_init<<<4096, 256>>>(x, ef0);
    k_hist<<<Ee / 256, 256>>>(eidx, etyp);
    k_scanA<<<16, 1024>>>();
    k_scanB<<<1, 32>>>();
    k_scanC<<<16, 1024>>>();
    k_scatter<<<Ee / 256, 256>>>();

    for (int l = 0; l < Ll; l++) {
        k_rgef<<<1, 256>>>(theta, wr, l);
        k_gemm<<<dim3(Nn / 32, Tt), 256>>>(we, theta, l);
        k_soft<<<Nn / 4, 128>>>();
        k_agg<<<Nn, 256>>>(out, l == Ll - 1, l < Ll - 1);
    }
}

// round 4
// speedup vs baseline: 1.1784x; 1.1784x over previous
#include <cuda_runtime.h>
#include <math.h>

#define Nn 16384
#define Ee 262144
#define Tt 4
#define Dd 64
#define Ll 2
#define TND (Tt*Nn*Dd)
#define NEGINF (-3.4e38f)

// ---- scratch ----
__device__ int   g_rowr[Ee];        // raw row per edge
__device__ int   g_cet[Ee];         // raw packed (col | ty<<14) per edge
__device__ int   g_ect[Ee];         // CSR-sorted packed (col | ty<<14)
__device__ int   g_deg[Nn], g_off[Nn + 1], g_cur[Nn];
__device__ int   g_bsum[16], g_bbase[16];
__device__ float g_h[TND];          // node features (T,N,D)
__device__ float g_hw[TND];         // h @ we      (T,N,D)
__device__ float g_si[Tt * Nn], g_sj[Tt * Nn];
__device__ float g_ef[Tt * Dd];
__device__ float g_rg[Tt * Tt];
__device__ float g_vg[Tt * Dd];
__device__ int   g_is64;

// ---- dtype detect: int64 data always in [0,N); int32-as-int64 is not ----
__global__ void k_detect(const void* eidx) {
    __shared__ int bad;
    if (threadIdx.x == 0) bad = 0;
    __syncthreads();
    const long long* p = (const long long*)eidx;
    int b = 0;
#pragma unroll
    for (int k = 0; k < 4; k++) {
        long long v = p[threadIdx.x + k * 256];
        if (v < 0 || v >= Nn) b = 1;
    }
    if (b) atomicExch(&bad, 1);
    __syncthreads();
    if (threadIdx.x == 0) g_is64 = !bad;
}

__global__ void k_init(const float* __restrict__ x, const float* __restrict__ ef0) {
    int i = blockIdx.x * blockDim.x + threadIdx.x;
    int stride = gridDim.x * blockDim.x;
    for (int j = i; j < TND; j += stride) g_h[j] = x[j & (Nn * Dd - 1)];
    if (i < Tt * Dd) g_ef[i] = ef0[i];
    for (int j = i; j < Nn; j += stride) g_deg[j] = 0;
}

__global__ void k_hist(const void* __restrict__ eidx, const void* __restrict__ etyp) {
    int e = blockIdx.x * blockDim.x + threadIdx.x;
    if (e >= Ee) return;
    int r, c, t;
    if (g_is64) {
        r = (int)((const long long*)eidx)[e];
        c = (int)((const long long*)eidx)[Ee + e];
        t = (int)((const long long*)etyp)[e];
    } else {
        r = ((const int*)eidx)[e];
        c = ((const int*)eidx)[Ee + e];
        t = ((const int*)etyp)[e];
    }
    g_rowr[e] = r;
    g_cet[e]  = c | (t << 14);
    atomicAdd(&g_deg[r], 1);
}

// ---- parallel 3-phase exclusive scan ----
__global__ void k_scanA() {
    __shared__ int sh[1024];
    int b = blockIdx.x, tid = threadIdx.x;
    int i = b * 1024 + tid;
    int v = g_deg[i];
    sh[tid] = v;
    __syncthreads();
    for (int off = 1; off < 1024; off <<= 1) {
        int u = (tid >= off) ? sh[tid - off] : 0;
        __syncthreads();
        sh[tid] += u;
        __syncthreads();
    }
    g_off[i] = sh[tid] - v;
    if (tid == 1023) g_bsum[b] = sh[tid];
}

__global__ void k_scanB() {
    int tid = threadIdx.x;
    int v = (tid < 16) ? g_bsum[tid] : 0;
    int inc = v;
#pragma unroll
    for (int off = 1; off < 32; off <<= 1) {
        int u = __shfl_up_sync(0xffffffffu, inc, off);
        if (tid >= off) inc += u;
    }
    if (tid < 16) g_bbase[tid] = inc - v;
}

__global__ void k_scanC() {
    int b = blockIdx.x, tid = threadIdx.x;
    int i = b * 1024 + tid;
    int o = g_off[i] + g_bbase[b];
    g_off[i] = o;
    g_cur[i] = o;
    if (i == 0) g_off[Nn] = Ee;
}

__global__ void k_scatter() {
    int e = blockIdx.x * blockDim.x + threadIdx.x;
    if (e >= Ee) return;
    int pos = atomicAdd(&g_cur[g_rowr[e]], 1);
    g_ect[pos] = g_cet[e];
}

// ---- per-layer tiny math: rg, vg, ef update ----
__global__ void k_rgef(const float* __restrict__ theta, const float* __restrict__ wr, int layer) {
    __shared__ float ef_s[Tt * Dd];
    int tid = threadIdx.x;              // 256
    ef_s[tid] = g_ef[tid];
    __syncthreads();
    const float* th = theta + (size_t)layer * Tt * 3 * Dd;
    if (tid < Tt * Tt) {
        int t1 = tid >> 2, t2 = tid & 3;
        const float* tg = th + t1 * 3 * Dd;
        float s = 0.f;
#pragma unroll
        for (int k = 0; k < Dd; k++) s += tg[k] * ef_s[t2 * Dd + k];
        g_rg[tid] = s;
    }
    {
        int t = tid >> 6, d = tid & 63;
        const float* w = wr + (size_t)layer * Dd * Dd;
        float s = 0.f;
#pragma unroll
        for (int k = 0; k < Dd; k++) s += ef_s[t * Dd + k] * w[k * Dd + d];
        g_vg[tid] = 1.f / (1.f + __expf(-s));
        g_ef[tid] = (layer < Ll - 1) ? fmaxf(s, 0.f) : s;
    }
}

// ---- GEMM (h @ we) fused with si/sj dots ----
__global__ void k_gemm(const float* __restrict__ we, const float* __restrict__ theta, int layer) {
    __shared__ float we_s[Dd * Dd];
    __shared__ float h_s[32 * Dd];
    __shared__ float thi_s[Dd], thj_s[Dd];
    int tid = threadIdx.x;              // 256
    int t = blockIdx.y;
    int n0 = blockIdx.x * 32;
    const float* w = we + (size_t)layer * Dd * Dd;
#pragma unroll
    for (int i = 0; i < 16; i++) we_s[tid + i * 256] = w[tid + i * 256];
    const float* hb = g_h + (size_t)t * Nn * Dd + (size_t)n0 * Dd;
#pragma unroll
    for (int i = 0; i < 8; i++) h_s[tid + i * 256] = hb[tid + i * 256];
    const float* th = theta + (size_t)layer * Tt * 3 * Dd + t * 3 * Dd;
    if (tid < Dd) thi_s[tid] = th[Dd + tid];
    else if (tid < 2 * Dd) thj_s[tid - Dd] = th[Dd + tid];
    __syncthreads();
    int d = tid & 63, ng = tid >> 6;
    float acc[8] = {0.f, 0.f, 0.f, 0.f, 0.f, 0.f, 0.f, 0.f};
#pragma unroll
    for (int k = 0; k < Dd; k++) {
        float wv = we_s[k * Dd + d];
#pragma unroll
        for (int j = 0; j < 8; j++) acc[j] += h_s[(ng * 8 + j) * Dd + k] * wv;
    }
    float* ob = g_hw + (size_t)t * Nn * Dd + (size_t)n0 * Dd;
#pragma unroll
    for (int j = 0; j < 8; j++) ob[(ng * 8 + j) * Dd + d] = acc[j];

    int wid = tid >> 5, lane = tid & 31;
#pragma unroll
    for (int j = 0; j < 4; j++) {
        int nl = wid * 4 + j;
        float a = h_s[nl * Dd + lane], b = h_s[nl * Dd + lane + 32];
        float si = a * thi_s[lane] + b * thi_s[lane + 32];
        float sj = a * thj_s[lane] + b * thj_s[lane + 32];
#pragma unroll
        for (int o = 16; o; o >>= 1) {
            si += __shfl_down_sync(0xffffffffu, si, o);
            sj += __shfl_down_sync(0xffffffffu, sj, o);
        }
        if (lane == 0) {
            g_si[t * Nn + n0 + nl] = si;
            g_sj[t * Nn + n0 + nl] = sj;
        }
    }
}

// ---- fused online softmax + aggregation: warp per (node, type) ----
__global__ void k_fused(float* __restrict__ out, int final_layer, int dorelu) {
    __shared__ float vg_s[Tt * Dd];
    __shared__ float rg_s[Tt * Tt];
    int tid = threadIdx.x;              // 256 = 8 warps = 2 nodes x 4 types
    vg_s[tid] = g_vg[tid];
    if (tid < Tt * Tt) rg_s[tid] = g_rg[tid];
    __syncthreads();
    int w = tid >> 5, lane = tid & 31;
    int n = blockIdx.x * 2 + (w >> 2);
    int t = w & 3;
    int beg = g_off[n], end = g_off[n + 1];
    float si = g_si[t * Nn + n];
    const float* hwt = g_hw + (size_t)t * (Nn * Dd);
    const float* sjt = g_sj + t * Nn;
    const float* rgt = rg_s + t * 4;
    float acc0 = 0.f, acc1 = 0.f, m = NEGINF, s = 0.f;

    for (int base = beg; base < end; base += 32) {
        int cnt = min(32, end - base);
        int e = base + lane;
        int pk = (lane < cnt) ? g_ect[e] : 0;
        int c  = pk & 16383;
        int ty = pk >> 14;
        float l = (lane < cnt) ? rgt[ty] + si + sjt[c] : NEGINF;
        float cm = l;
#pragma unroll
        for (int o = 16; o; o >>= 1) cm = fmaxf(cm, __shfl_xor_sync(0xffffffffu, cm, o));
        float newm = fmaxf(m, cm);
        float scale = __expf(m - newm);            // 0 on first chunk
        float p = (lane < cnt) ? __expf(l - newm) : 0.f;
        float ps = p;
#pragma unroll
        for (int o = 16; o; o >>= 1) ps += __shfl_xor_sync(0xffffffffu, ps, o);
        s = s * scale + ps;
        acc0 *= scale;
        acc1 *= scale;
#pragma unroll 4
        for (int i = 0; i < cnt; i++) {
            float pi = __shfl_sync(0xffffffffu, p, i);
            int   ci = __shfl_sync(0xffffffffu, c, i);
            int  tyi = __shfl_sync(0xffffffffu, ty, i);
            const float* hp = hwt + (size_t)ci * Dd;
            acc0 += pi * vg_s[tyi * Dd + lane]      * hp[lane];
            acc1 += pi * vg_s[tyi * Dd + 32 + lane] * hp[lane + 32];
        }
        m = newm;
    }

    float inv = s > 0.f ? 1.f / s : 0.f;
    float v0 = acc0 * inv, v1 = acc1 * inv;
    if (dorelu) { v0 = fmaxf(v0, 0.f); v1 = fmaxf(v1, 0.f); }
    float* dst = final_layer ? out : g_h;
    size_t ob = (size_t)t * (Nn * Dd) + (size_t)n * Dd;
    dst[ob + lane]      = v0;
    dst[ob + 32 + lane] = v1;
}

extern "C" void kernel_launch(void* const* d_in, const int* in_sizes, int n_in,
                              void* d_out, int out_size) {
    const float* x     = (const float*)d_in[0];
    const float* ef0   = (const float*)d_in[1];
    const float* theta = (const float*)d_in[2];
    const float* wr    = (const float*)d_in[3];
    const float* we    = (const float*)d_in[4];
    const void*  eidx  = d_in[5];
    const void*  etyp  = d_in[6];
    float* out = (float*)d_out;

    k_detect<<<1, 256>>>(eidx);
    k_init<<<4096, 256>>>(x, ef0);
    k_hist<<<Ee / 256, 256>>>(eidx, etyp);
    k_scanA<<<16, 1024>>>();
    k_scanB<<<1, 32>>>();
    k_scanC<<<16, 1024>>>();
    k_scatter<<<Ee / 256, 256>>>();

    for (int l = 0; l < Ll; l++) {
        k_rgef<<<1, 256>>>(theta, wr, l);
        k_gemm<<<dim3(Nn / 32, Tt), 256>>>(we, theta, l);
        k_fused<<<Nn / 2, 256>>>(out, l == Ll - 1, l < Ll - 1);
    }
}

// round 5
// speedup vs baseline: 1.4185x; 1.2037x over previous
#include <cuda_runtime.h>
#include <math.h>

#define Nn 16384
#define Ee 262144
#define Tt 4
#define Dd 64
#define Ll 2
#define TND (Tt*Nn*Dd)
#define NEGINF (-3.4e38f)

// ---- scratch ----
__device__ int   g_rowr[Ee];
__device__ int   g_cet[Ee];          // raw packed (col | ty<<14)
__device__ int   g_ect[Ee];          // CSR-sorted packed
__device__ int   g_deg[Nn], g_off[Nn + 1], g_cur[Nn];
__device__ int   g_bval[16];
__device__ int   g_bflag[16];
__device__ float g_h[TND];           // node features layer>=1 (T,N,D)
__device__ float g_hw[TND];          // h @ we (plane 0 only for layer 0)
__device__ float g_si[Tt * Nn], g_sj[Tt * Nn];
__device__ float g_ef[Tt * Dd];
__device__ float g_rg[Tt * Tt];
__device__ float g_vg[Tt * Dd];
__device__ int   g_is64;

// ---- pre: dtype detect + ef copy + zero deg/flags ----
__global__ void k_pre(const void* eidx, const float* __restrict__ ef0) {
    int tid = threadIdx.x;           // 256, grid 64
    if (blockIdx.x == 0) {
        __shared__ int bad;
        if (tid == 0) bad = 0;
        __syncthreads();
        const long long* p = (const long long*)eidx;
        int b = 0;
#pragma unroll
        for (int k = 0; k < 4; k++) {
            long long v = p[tid + k * 256];
            if (v < 0 || v >= Nn) b = 1;
        }
        if (b) atomicExch(&bad, 1);
        __syncthreads();
        if (tid == 0) g_is64 = !bad;
        g_ef[tid] = ef0[tid];
        if (tid < 16) g_bflag[tid] = 0;
    }
    g_deg[blockIdx.x * 256 + tid] = 0;
}

__global__ void k_hist(const void* __restrict__ eidx, const void* __restrict__ etyp) {
    int e = blockIdx.x * blockDim.x + threadIdx.x;
    if (e >= Ee) return;
    int r, c, t;
    if (g_is64) {
        r = (int)((const long long*)eidx)[e];
        c = (int)((const long long*)eidx)[Ee + e];
        t = (int)((const long long*)etyp)[e];
    } else {
        r = ((const int*)eidx)[e];
        c = ((const int*)eidx)[Ee + e];
        t = ((const int*)etyp)[e];
    }
    g_rowr[e] = r;
    g_cet[e]  = c | (t << 14);
    atomicAdd(&g_deg[r], 1);
}

// ---- single-kernel exclusive scan, 16 blocks, decoupled lookback ----
__global__ void k_scan() {
    __shared__ int sh[1024];
    __shared__ int base_s;
    int b = blockIdx.x, tid = threadIdx.x;
    int i = b * 1024 + tid;
    int v = g_deg[i];
    sh[tid] = v;
    __syncthreads();
    for (int off = 1; off < 1024; off <<= 1) {
        int u = (tid >= off) ? sh[tid - off] : 0;
        __syncthreads();
        sh[tid] += u;
        __syncthreads();
    }
    if (tid == 1023) {
        g_bval[b] = sh[1023];
        __threadfence();
        atomicExch(&g_bflag[b], 1);
    }
    if (tid == 0) {
        int acc = 0;
        for (int j = 0; j < b; j++) {
            while (atomicAdd(&g_bflag[j], 0) == 0) { }
            acc += g_bval[j];
        }
        base_s = acc;
    }
    __syncthreads();
    int o = sh[tid] - v + base_s;
    g_off[i] = o;
    g_cur[i] = o;
    if (i == 0) g_off[Nn] = Ee;
}

__global__ void k_scatter() {
    int e = blockIdx.x * blockDim.x + threadIdx.x;
    if (e >= Ee) return;
    int pos = atomicAdd(&g_cur[g_rowr[e]], 1);
    g_ect[pos] = g_cet[e];
}

// ---- rgef body (runs in one block of the gemm kernels) ----
__device__ void rgef_body(const float* __restrict__ theta, const float* __restrict__ wr, int layer) {
    __shared__ float ef_s[Tt * Dd];
    int tid = threadIdx.x;              // 256
    ef_s[tid] = g_ef[tid];
    __syncthreads();
    const float* th = theta + (size_t)layer * Tt * 3 * Dd;
    if (tid < Tt * Tt) {
        int t1 = tid >> 2, t2 = tid & 3;
        const float* tg = th + t1 * 3 * Dd;
        float s = 0.f;
#pragma unroll
        for (int k = 0; k < Dd; k++) s += tg[k] * ef_s[t2 * Dd + k];
        g_rg[tid] = s;
    }
    {
        int t = tid >> 6, d = tid & 63;
        const float* w = wr + (size_t)layer * Dd * Dd;
        float s = 0.f;
#pragma unroll
        for (int k = 0; k < Dd; k++) s += ef_s[t * Dd + k] * w[k * Dd + d];
        g_vg[tid] = 1.f / (1.f + __expf(-s));
        g_ef[tid] = (layer < Ll - 1) ? fmaxf(s, 0.f) : s;
    }
}

// ---- layer-0 gemm: h == broadcast(x); hw computed ONCE (plane 0); si/sj for all 4 t ----
__global__ void k_gemm0(const float* __restrict__ x, const float* __restrict__ we,
                        const float* __restrict__ theta, const float* __restrict__ wr) {
    if (blockIdx.x == Nn / 32) { rgef_body(theta, wr, 0); return; }
    __shared__ float we_s[Dd * Dd];
    __shared__ float h_s[32 * Dd];
    __shared__ float thi_s[Tt * Dd], thj_s[Tt * Dd];
    int tid = threadIdx.x;              // 256
    int n0 = blockIdx.x * 32;
    const float* w = we;                // layer 0
#pragma unroll
    for (int i = 0; i < 16; i++) we_s[tid + i * 256] = w[tid + i * 256];
    const float* hb = x + (size_t)n0 * Dd;
#pragma unroll
    for (int i = 0; i < 8; i++) h_s[tid + i * 256] = hb[tid + i * 256];
    {   // theta[0, t, Dd:3Dd]: for each t copy thi (64) and thj (64)
        int t = tid >> 6, d = tid & 63;
        const float* th = theta + t * 3 * Dd;
        thi_s[t * Dd + d] = th[Dd + d];
        thj_s[t * Dd + d] = th[2 * Dd + d];
    }
    __syncthreads();
    int d = tid & 63, ng = tid >> 6;
    float acc[8] = {0.f, 0.f, 0.f, 0.f, 0.f, 0.f, 0.f, 0.f};
#pragma unroll
    for (int k = 0; k < Dd; k++) {
        float wv = we_s[k * Dd + d];
#pragma unroll
        for (int j = 0; j < 8; j++) acc[j] += h_s[(ng * 8 + j) * Dd + k] * wv;
    }
    float* ob = g_hw + (size_t)n0 * Dd;  // plane 0 only
#pragma unroll
    for (int j = 0; j < 8; j++) ob[(ng * 8 + j) * Dd + d] = acc[j];

    // si/sj for all (node, t): 8 warps x (4 nodes x 4 t)
    int wid = tid >> 5, lane = tid & 31;
#pragma unroll
    for (int j = 0; j < 4; j++) {
        int nl = wid * 4 + j;
        float a = h_s[nl * Dd + lane], b = h_s[nl * Dd + lane + 32];
#pragma unroll
        for (int t = 0; t < Tt; t++) {
            float si = a * thi_s[t * Dd + lane] + b * thi_s[t * Dd + lane + 32];
            float sj = a * thj_s[t * Dd + lane] + b * thj_s[t * Dd + lane + 32];
#pragma unroll
            for (int o = 16; o; o >>= 1) {
                si += __shfl_down_sync(0xffffffffu, si, o);
                sj += __shfl_down_sync(0xffffffffu, sj, o);
            }
            if (lane == 0) {
                g_si[t * Nn + n0 + nl] = si;
                g_sj[t * Nn + n0 + nl] = sj;
            }
        }
    }
}

// ---- layer>=1 gemm (per t-plane) fused with si/sj + rgef block ----
__global__ void k_gemm1(const float* __restrict__ we, const float* __restrict__ theta,
                        const float* __restrict__ wr, int layer) {
    if (blockIdx.x == Nn / 32) {
        if (blockIdx.y == 0) rgef_body(theta, wr, layer);
        return;
    }
    __shared__ float we_s[Dd * Dd];
    __shared__ float h_s[32 * Dd];
    __shared__ float thi_s[Dd], thj_s[Dd];
    int tid = threadIdx.x;              // 256
    int t = blockIdx.y;
    int n0 = blockIdx.x * 32;
    const float* w = we + (size_t)layer * Dd * Dd;
#pragma unroll
    for (int i = 0; i < 16; i++) we_s[tid + i * 256] = w[tid + i * 256];
    const float* hb = g_h + (size_t)t * Nn * Dd + (size_t)n0 * Dd;
#pragma unroll
    for (int i = 0; i < 8; i++) h_s[tid + i * 256] = hb[tid + i * 256];
    const float* th = theta + (size_t)layer * Tt * 3 * Dd + t * 3 * Dd;
    if (tid < Dd) thi_s[tid] = th[Dd + tid];
    else if (tid < 2 * Dd) thj_s[tid - Dd] = th[Dd + tid];
    __syncthreads();
    int d = tid & 63, ng = tid >> 6;
    float acc[8] = {0.f, 0.f, 0.f, 0.f, 0.f, 0.f, 0.f, 0.f};
#pragma unroll
    for (int k = 0; k < Dd; k++) {
        float wv = we_s[k * Dd + d];
#pragma unroll
        for (int j = 0; j < 8; j++) acc[j] += h_s[(ng * 8 + j) * Dd + k] * wv;
    }
    float* ob = g_hw + (size_t)t * Nn * Dd + (size_t)n0 * Dd;
#pragma unroll
    for (int j = 0; j < 8; j++) ob[(ng * 8 + j) * Dd + d] = acc[j];

    int wid = tid >> 5, lane = tid & 31;
#pragma unroll
    for (int j = 0; j < 4; j++) {
        int nl = wid * 4 + j;
        float a = h_s[nl * Dd + lane], b = h_s[nl * Dd + lane + 32];
        float si = a * thi_s[lane] + b * thi_s[lane + 32];
        float sj = a * thj_s[lane] + b * thj_s[lane + 32];
#pragma unroll
        for (int o = 16; o; o >>= 1) {
            si += __shfl_down_sync(0xffffffffu, si, o);
            sj += __shfl_down_sync(0xffffffffu, sj, o);
        }
        if (lane == 0) {
            g_si[t * Nn + n0 + nl] = si;
            g_sj[t * Nn + n0 + nl] = sj;
        }
    }
}

// ---- fused online softmax + aggregation: warp per (node, type) ----
__global__ void k_fused(float* __restrict__ out, int hw_stride, int final_layer, int dorelu) {
    __shared__ float vg_s[Tt * Dd];
    __shared__ float rg_s[Tt * Tt];
    __shared__ uint2 spp[8][32];
    int tid = threadIdx.x;              // 256 = 8 warps = 2 nodes x 4 types
    vg_s[tid] = g_vg[tid];
    if (tid < Tt * Tt) rg_s[tid] = g_rg[tid];
    __syncthreads();
    int w = tid >> 5, lane = tid & 31;
    int n = blockIdx.x * 2 + (w >> 2);
    int t = w & 3;
    int beg = g_off[n], end = g_off[n + 1];
    float si = g_si[t * Nn + n];
    const float* hwt = g_hw + (size_t)t * hw_stride;
    const float* sjt = g_sj + t * Nn;
    const float* rgt = rg_s + t * 4;
    uint2* myspp = spp[w];
    float acc0 = 0.f, acc1 = 0.f, m = NEGINF, s = 0.f;

    for (int base = beg; base < end; base += 32) {
        int cnt = min(32, end - base);
        int pk = (lane < cnt) ? g_ect[base + lane] : 0;
        float l = (lane < cnt) ? rgt[pk >> 14] + si + sjt[pk & 16383] : NEGINF;
        float cm = l;
#pragma unroll
        for (int o = 16; o; o >>= 1) cm = fmaxf(cm, __shfl_xor_sync(0xffffffffu, cm, o));
        float newm = fmaxf(m, cm);
        float scale = __expf(m - newm);
        float p = (lane < cnt) ? __expf(l - newm) : 0.f;
        float ps = p;
#pragma unroll
        for (int o = 16; o; o >>= 1) ps += __shfl_xor_sync(0xffffffffu, ps, o);
        s = s * scale + ps;
        acc0 *= scale;
        acc1 *= scale;
        myspp[lane] = make_uint2(__float_as_uint(p), (unsigned)pk);
        __syncwarp();
#pragma unroll 4
        for (int i = 0; i < cnt; i++) {
            uint2 q = myspp[i];
            float pi = __uint_as_float(q.x);
            int ci = q.y & 16383, tyi = q.y >> 14;
            const float* hp = hwt + (size_t)ci * Dd;
            acc0 += pi * vg_s[tyi * Dd + lane]      * hp[lane];
            acc1 += pi * vg_s[tyi * Dd + 32 + lane] * hp[lane + 32];
        }
        __syncwarp();
        m = newm;
    }

    float inv = s > 0.f ? 1.f / s : 0.f;
    float v0 = acc0 * inv, v1 = acc1 * inv;
    if (dorelu) { v0 = fmaxf(v0, 0.f); v1 = fmaxf(v1, 0.f); }
    float* dst = final_layer ? out : g_h;
    size_t ob = (size_t)t * (Nn * Dd) + (size_t)n * Dd;
    dst[ob + lane]      = v0;
    dst[ob + 32 + lane] = v1;
}

extern "C" void kernel_launch(void* const* d_in, const int* in_sizes, int n_in,
                              void* d_out, int out_size) {
    const float* x     = (const float*)d_in[0];
    const float* ef0   = (const float*)d_in[1];
    const float* theta = (const float*)d_in[2];
    const float* wr    = (const float*)d_in[3];
    const float* we    = (const float*)d_in[4];
    const void*  eidx  = d_in[5];
    const void*  etyp  = d_in[6];
    float* out = (float*)d_out;

    k_pre<<<64, 256>>>(eidx, ef0);
    k_hist<<<Ee / 256, 256>>>(eidx, etyp);
    k_scan<<<16, 1024>>>();
    k_scatter<<<Ee / 256, 256>>>();

    // layer 0: h == broadcast(x) -> single hw plane
    k_gemm0<<<Nn / 32 + 1, 256>>>(x, we, theta, wr);
    k_fused<<<Nn / 2, 256>>>(out, 0, 0, 1);
    // layer 1
    k_gemm1<<<dim3(Nn / 32 + 1, Tt), 256>>>(we, theta, wr, 1);
    k_fused<<<Nn / 2, 256>>>(out, Nn * Dd, 1, 0);
}

// round 6
// speedup vs baseline: 1.5507x; 1.0932x over previous
#include <cuda_runtime.h>
#include <math.h>

#define Nn 16384
#define Ee 262144
#define Tt 4
#define Dd 64
#define Ll 2
#define TND (Tt*Nn*Dd)
#define NEGINF (-3.4e38f)

// ---- scratch ----
__device__ int   g_rowr[Ee];
__device__ int   g_cet[Ee];           // raw packed (col | ty<<14)
__device__ int   g_ect[Ee];           // CSR-sorted packed
__device__ int   g_deg[Nn], g_off[Nn + 1], g_cur[Nn];
__device__ int   g_bval[16], g_bflag[16];
__device__ float g_hw0[Nn * Dd];      // x @ we0 (single plane; layer-0 h is broadcast)
__device__ float g_hw1[TND];          // h1 @ we1 (T,N,D)
__device__ float g_sj0[Nn * Tt];      // interleaved [n][t]
__device__ float g_sj1[Nn * Tt];
__device__ float g_rg[2][Tt * Tt];
__device__ float g_vg[2][Tt * Dd];
__device__ int   g_is64;

// ---- pre: dtype detect + zero deg/flags ----
__global__ void k_pre(const void* eidx) {
    int tid = threadIdx.x;            // 256, grid 64
    if (blockIdx.x == 0) {
        __shared__ int bad;
        if (tid == 0) bad = 0;
        __syncthreads();
        const long long* p = (const long long*)eidx;
        int b = 0;
#pragma unroll
        for (int k = 0; k < 4; k++) {
            long long v = p[tid + k * 256];
            if (v < 0 || v >= Nn) b = 1;
        }
        if (b) atomicExch(&bad, 1);
        __syncthreads();
        if (tid == 0) g_is64 = !bad;
        if (tid < 16) g_bflag[tid] = 0;
    }
    g_deg[blockIdx.x * 256 + tid] = 0;
}

__global__ void k_hist(const void* __restrict__ eidx, const void* __restrict__ etyp) {
    int e = blockIdx.x * blockDim.x + threadIdx.x;
    if (e >= Ee) return;
    int r, c, t;
    if (g_is64) {
        r = (int)((const long long*)eidx)[e];
        c = (int)((const long long*)eidx)[Ee + e];
        t = (int)((const long long*)etyp)[e];
    } else {
        r = ((const int*)eidx)[e];
        c = ((const int*)eidx)[Ee + e];
        t = ((const int*)etyp)[e];
    }
    g_rowr[e] = r;
    g_cet[e]  = c | (t << 14);
    atomicAdd(&g_deg[r], 1);
}

// ---- single-kernel exclusive scan, 16 blocks, decoupled lookback ----
__global__ void k_scan() {
    __shared__ int sh[1024];
    __shared__ int base_s;
    int b = blockIdx.x, tid = threadIdx.x;
    int i = b * 1024 + tid;
    int v = g_deg[i];
    sh[tid] = v;
    __syncthreads();
    for (int off = 1; off < 1024; off <<= 1) {
        int u = (tid >= off) ? sh[tid - off] : 0;
        __syncthreads();
        sh[tid] += u;
        __syncthreads();
    }
    if (tid == 1023) {
        g_bval[b] = sh[1023];
        __threadfence();
        atomicExch(&g_bflag[b], 1);
    }
    if (tid == 0) {
        int acc = 0;
        for (int j = 0; j < b; j++) {
            while (atomicAdd(&g_bflag[j], 0) == 0) { }
            acc += g_bval[j];
        }
        base_s = acc;
    }
    __syncthreads();
    int o = sh[tid] - v + base_s;
    g_off[i] = o;
    g_cur[i] = o;
    if (i == 0) g_off[Nn] = Ee;
}

__global__ void k_scatter() {
    int i = blockIdx.x * blockDim.x + threadIdx.x;   // 2 edges per thread
#pragma unroll
    for (int k = 0; k < 2; k++) {
        int e = i * 2 + k;
        int pos = atomicAdd(&g_cur[g_rowr[e]], 1);
        g_ect[pos] = g_cet[e];
    }
}

// ---- rgef for BOTH layers (one block) ----
__device__ void rgef_body(const float* __restrict__ ef0, const float* __restrict__ theta,
                          const float* __restrict__ wr) {
    __shared__ float efa[Tt * Dd], efb[Tt * Dd];
    int tid = threadIdx.x;              // 256
    int t = tid >> 6, d = tid & 63;
    efa[tid] = ef0[tid];
    __syncthreads();
    // rg0
    if (tid < Tt * Tt) {
        int t1 = tid >> 2, t2 = tid & 3;
        const float* tg = theta + t1 * 3 * Dd;
        float s = 0.f;
#pragma unroll
        for (int k = 0; k < Dd; k++) s += tg[k] * efa[t2 * Dd + k];
        g_rg[0][tid] = s;
    }
    // ef1 = ef0 @ wr0 ; vg0 = sigmoid ; efb = relu
    {
        float s = 0.f;
#pragma unroll
        for (int k = 0; k < Dd; k++) s += efa[t * Dd + k] * wr[k * Dd + d];
        g_vg[0][tid] = 1.f / (1.f + __expf(-s));
        efb[tid] = fmaxf(s, 0.f);
    }
    __syncthreads();
    // rg1
    if (tid < Tt * Tt) {
        int t1 = tid >> 2, t2 = tid & 3;
        const float* tg = theta + (Tt * 3 * Dd) + t1 * 3 * Dd;
        float s = 0.f;
#pragma unroll
        for (int k = 0; k < Dd; k++) s += tg[k] * efb[t2 * Dd + k];
        g_rg[1][tid] = s;
    }
    // vg1 = sigmoid(efb @ wr1)
    {
        const float* w1 = wr + Dd * Dd;
        float s = 0.f;
#pragma unroll
        for (int k = 0; k < Dd; k++) s += efb[t * Dd + k] * w1[k * Dd + d];
        g_vg[1][tid] = 1.f / (1.f + __expf(-s));
    }
}

// ---- layer-0 gemm: hw0 = x @ we0 (once) + sj0 for all 4 t + rgef both layers ----
__global__ void k_gemm0(const float* __restrict__ x, const float* __restrict__ ef0,
                        const float* __restrict__ we, const float* __restrict__ theta,
                        const float* __restrict__ wr) {
    if (blockIdx.x == Nn / 32) { rgef_body(ef0, theta, wr); return; }
    __shared__ float we_s[Dd * Dd];
    __shared__ float h_s[32 * Dd];
    __shared__ float thj_s[Tt * Dd];
    int tid = threadIdx.x;              // 256
    int n0 = blockIdx.x * 32;
#pragma unroll
    for (int i = 0; i < 16; i++) we_s[tid + i * 256] = we[tid + i * 256];
    const float* hb = x + (size_t)n0 * Dd;
#pragma unroll
    for (int i = 0; i < 8; i++) h_s[tid + i * 256] = hb[tid + i * 256];
    {
        int t = tid >> 6, d = tid & 63;
        thj_s[t * Dd + d] = theta[t * 3 * Dd + 2 * Dd + d];
    }
    __syncthreads();
    int d = tid & 63, ng = tid >> 6;
    float acc[8] = {0.f, 0.f, 0.f, 0.f, 0.f, 0.f, 0.f, 0.f};
#pragma unroll
    for (int k = 0; k < Dd; k++) {
        float wv = we_s[k * Dd + d];
#pragma unroll
        for (int j = 0; j < 8; j++) acc[j] += h_s[(ng * 8 + j) * Dd + k] * wv;
    }
    float* ob = g_hw0 + (size_t)n0 * Dd;
#pragma unroll
    for (int j = 0; j < 8; j++) ob[(ng * 8 + j) * Dd + d] = acc[j];

    int wid = tid >> 5, lane = tid & 31;
#pragma unroll
    for (int j = 0; j < 4; j++) {
        int nl = wid * 4 + j;
        float a = h_s[nl * Dd + lane], b = h_s[nl * Dd + lane + 32];
#pragma unroll
        for (int t = 0; t < Tt; t++) {
            float sj = a * thj_s[t * Dd + lane] + b * thj_s[t * Dd + lane + 32];
#pragma unroll
            for (int o = 16; o; o >>= 1) sj += __shfl_down_sync(0xffffffffu, sj, o);
            if (lane == 0) g_sj0[(n0 + nl) * Tt + t] = sj;
        }
    }
}

// ---- fused layer 0: warp per NODE (4 online softmaxes), shared hw0 gather,
//      epilogue computes hw1 = relu(h1) @ we1 and sj1 (layer-1 inputs) ----
__global__ void k_fused0(const float* __restrict__ theta, const float* __restrict__ we) {
    __shared__ float vg_s[Tt * Dd];
    __shared__ float rg_s[Tt * Tt];
    __shared__ float we1_s[Dd * Dd];
    __shared__ float thj1_s[Tt * Dd];
    __shared__ float4 p4_s[8][32];
    __shared__ int   pk_s[8][32];
    __shared__ float h_s[8][Dd];
    int tid = threadIdx.x;              // 256 = 8 warps = 8 nodes
    vg_s[tid] = g_vg[0][tid];
    if (tid < Tt * Tt) rg_s[tid] = g_rg[0][tid];
    const float* w1 = we + Dd * Dd;
#pragma unroll
    for (int i = 0; i < 16; i++) we1_s[tid + i * 256] = w1[tid + i * 256];
    {
        int t = tid >> 6, d = tid & 63;
        thj1_s[t * Dd + d] = theta[(Tt * 3 * Dd) + t * 3 * Dd + 2 * Dd + d];
    }
    __syncthreads();
    int w = tid >> 5, lane = tid & 31;
    int n = blockIdx.x * 8 + w;
    int beg = g_off[n], end = g_off[n + 1];
    const float4* sj4p = (const float4*)g_sj0;
    float a0l = 0.f, a0h = 0.f, a1l = 0.f, a1h = 0.f;
    float a2l = 0.f, a2h = 0.f, a3l = 0.f, a3h = 0.f;
    float m0 = NEGINF, m1 = NEGINF, m2 = NEGINF, m3 = NEGINF;
    float s0 = 0.f, s1 = 0.f, s2 = 0.f, s3 = 0.f;

    for (int base = beg; base < end; base += 32) {
        int cnt = min(32, end - base);
        int pk = 0; float4 sj4 = make_float4(0.f, 0.f, 0.f, 0.f);
        if (lane < cnt) { pk = g_ect[base + lane]; sj4 = sj4p[pk & 16383]; }
        int ty = pk >> 14;
        float l0, l1, l2, l3;
        if (lane < cnt) {
            l0 = rg_s[0 * 4 + ty] + sj4.x;
            l1 = rg_s[1 * 4 + ty] + sj4.y;
            l2 = rg_s[2 * 4 + ty] + sj4.z;
            l3 = rg_s[3 * 4 + ty] + sj4.w;
        } else { l0 = l1 = l2 = l3 = NEGINF; }
        float c0 = l0, c1 = l1, c2 = l2, c3 = l3;
#pragma unroll
        for (int o = 16; o; o >>= 1) {
            c0 = fmaxf(c0, __shfl_xor_sync(0xffffffffu, c0, o));
            c1 = fmaxf(c1, __shfl_xor_sync(0xffffffffu, c1, o));
            c2 = fmaxf(c2, __shfl_xor_sync(0xffffffffu, c2, o));
            c3 = fmaxf(c3, __shfl_xor_sync(0xffffffffu, c3, o));
        }
        float nm0 = fmaxf(m0, c0), nm1 = fmaxf(m1, c1), nm2 = fmaxf(m2, c2), nm3 = fmaxf(m3, c3);
        float sc0 = __expf(m0 - nm0), sc1 = __expf(m1 - nm1), sc2 = __expf(m2 - nm2), sc3 = __expf(m3 - nm3);
        float p0 = (lane < cnt) ? __expf(l0 - nm0) : 0.f;
        float p1 = (lane < cnt) ? __expf(l1 - nm1) : 0.f;
        float p2 = (lane < cnt) ? __expf(l2 - nm2) : 0.f;
        float p3 = (lane < cnt) ? __expf(l3 - nm3) : 0.f;
        float q0 = p0, q1 = p1, q2 = p2, q3 = p3;
#pragma unroll
        for (int o = 16; o; o >>= 1) {
            q0 += __shfl_xor_sync(0xffffffffu, q0, o);
            q1 += __shfl_xor_sync(0xffffffffu, q1, o);
            q2 += __shfl_xor_sync(0xffffffffu, q2, o);
            q3 += __shfl_xor_sync(0xffffffffu, q3, o);
        }
        s0 = s0 * sc0 + q0; s1 = s1 * sc1 + q1; s2 = s2 * sc2 + q2; s3 = s3 * sc3 + q3;
        a0l *= sc0; a0h *= sc0; a1l *= sc1; a1h *= sc1;
        a2l *= sc2; a2h *= sc2; a3l *= sc3; a3h *= sc3;
        p4_s[w][lane] = make_float4(p0, p1, p2, p3);
        pk_s[w][lane] = pk;
        __syncwarp();
#pragma unroll 4
        for (int i = 0; i < cnt; i++) {
            float4 p = p4_s[w][i];
            int pki = pk_s[w][i];
            int ci = pki & 16383, tyi = pki >> 14;
            const float* hp = g_hw0 + (size_t)ci * Dd;
            float hl = hp[lane], hh = hp[lane + 32];
            float vl = vg_s[tyi * Dd + lane] * hl;
            float vh = vg_s[tyi * Dd + 32 + lane] * hh;
            a0l += p.x * vl; a0h += p.x * vh;
            a1l += p.y * vl; a1h += p.y * vh;
            a2l += p.z * vl; a2h += p.z * vh;
            a3l += p.w * vl; a3h += p.w * vh;
        }
        __syncwarp();
        m0 = nm0; m1 = nm1; m2 = nm2; m3 = nm3;
    }

    // epilogue per t: h1 = relu(acc/s) -> hw1, sj1
    float accl[Tt] = {a0l, a1l, a2l, a3l};
    float acch[Tt] = {a0h, a1h, a2h, a3h};
    float ss[Tt] = {s0, s1, s2, s3};
#pragma unroll
    for (int t = 0; t < Tt; t++) {
        float inv = ss[t] > 0.f ? 1.f / ss[t] : 0.f;
        float v0 = fmaxf(accl[t] * inv, 0.f);
        float v1 = fmaxf(acch[t] * inv, 0.f);
        h_s[w][lane] = v0; h_s[w][lane + 32] = v1;
        __syncwarp();
        float o0 = 0.f, o1 = 0.f;
#pragma unroll
        for (int k = 0; k < Dd; k++) {
            float hv = h_s[w][k];
            o0 += hv * we1_s[k * Dd + lane];
            o1 += hv * we1_s[k * Dd + lane + 32];
        }
        size_t ob = (size_t)t * (Nn * Dd) + (size_t)n * Dd;
        g_hw1[ob + lane] = o0;
        g_hw1[ob + 32 + lane] = o1;
        float sj = v0 * thj1_s[t * Dd + lane] + v1 * thj1_s[t * Dd + lane + 32];
#pragma unroll
        for (int o = 16; o; o >>= 1) sj += __shfl_down_sync(0xffffffffu, sj, o);
        if (lane == 0) g_sj1[n * Tt + t] = sj;
        __syncwarp();
    }
}

// ---- fused layer 1: warp per (node, type) -> out ----
__global__ void k_fused1(float* __restrict__ out) {
    __shared__ float vg_s[Tt * Dd];
    __shared__ float rg_s[Tt * Tt];
    __shared__ uint2 spp[8][32];
    int tid = threadIdx.x;              // 256 = 2 nodes x 4 types
    vg_s[tid] = g_vg[1][tid];
    if (tid < Tt * Tt) rg_s[tid] = g_rg[1][tid];
    __syncthreads();
    int w = tid >> 5, lane = tid & 31;
    int n = blockIdx.x * 2 + (w >> 2);
    int t = w & 3;
    int beg = g_off[n], end = g_off[n + 1];
    const float* hwt = g_hw1 + (size_t)t * (Nn * Dd);
    const float* rgt = rg_s + t * 4;
    uint2* myspp = spp[w];
    float acc0 = 0.f, acc1 = 0.f, m = NEGINF, s = 0.f;

    for (int base = beg; base < end; base += 32) {
        int cnt = min(32, end - base);
        int pk = (lane < cnt) ? g_ect[base + lane] : 0;
        float l = (lane < cnt) ? rgt[pk >> 14] + g_sj1[(pk & 16383) * Tt + t] : NEGINF;
        float cm = l;
#pragma unroll
        for (int o = 16; o; o >>= 1) cm = fmaxf(cm, __shfl_xor_sync(0xffffffffu, cm, o));
        float newm = fmaxf(m, cm);
        float scale = __expf(m - newm);
        float p = (lane < cnt) ? __expf(l - newm) : 0.f;
        float ps = p;
#pragma unroll
        for (int o = 16; o; o >>= 1) ps += __shfl_xor_sync(0xffffffffu, ps, o);
        s = s * scale + ps;
        acc0 *= scale;
        acc1 *= scale;
        myspp[lane] = make_uint2(__float_as_uint(p), (unsigned)pk);
        __syncwarp();
#pragma unroll 4
        for (int i = 0; i < cnt; i++) {
            uint2 q = myspp[i];
            float pi = __uint_as_float(q.x);
            int ci = q.y & 16383, tyi = q.y >> 14;
            const float* hp = hwt + (size_t)ci * Dd;
            acc0 += pi * vg_s[tyi * Dd + lane]      * hp[lane];
            acc1 += pi * vg_s[tyi * Dd + 32 + lane] * hp[lane + 32];
        }
        __syncwarp();
        m = newm;
    }

    float inv = s > 0.f ? 1.f / s : 0.f;
    size_t ob = (size_t)t * (Nn * Dd) + (size_t)n * Dd;
    out[ob + lane]      = acc0 * inv;
    out[ob + 32 + lane] = acc1 * inv;
}

extern "C" void kernel_launch(void* const* d_in, const int* in_sizes, int n_in,
                              void* d_out, int out_size) {
    const float* x     = (const float*)d_in[0];
    const float* ef0   = (const float*)d_in[1];
    const float* theta = (const float*)d_in[2];
    const float* wr    = (const float*)d_in[3];
    const float* we    = (const float*)d_in[4];
    const void*  eidx  = d_in[5];
    const void*  etyp  = d_in[6];
    float* out = (float*)d_out;

    k_pre<<<64, 256>>>(eidx);
    k_hist<<<Ee / 256, 256>>>(eidx, etyp);
    k_scan<<<16, 1024>>>();
    k_scatter<<<Ee / 512, 256>>>();
    k_gemm0<<<Nn / 32 + 1, 256>>>(x, ef0, we, theta, wr);
    k_fused0<<<Nn / 8, 256>>>(theta, we);
    k_fused1<<<Nn / 2, 256>>>(out);
}

// round 7
// speedup vs baseline: 1.6366x; 1.0554x over previous
#include <cuda_runtime.h>
#include <math.h>

#define Nn 16384
#define Ee 262144
#define Tt 4
#define Dd 64
#define TND (Tt*Nn*Dd)

// ---- scratch ----
__device__ int   g_rr[Ee];            // packed (row | rank<<14)
__device__ int   g_cet[Ee];           // raw packed (col | ty<<14)
__device__ int   g_ect[Ee];           // CSR-sorted packed
__device__ int   g_deg[Nn], g_off[Nn + 1];
__device__ int   g_bval[16], g_bflag[16];
__device__ float g_hw0[Nn * Dd];      // x @ we0 (single plane; layer-0 h is broadcast)
__device__ float g_hw1[TND];          // h1 @ we1 (T,N,D)
__device__ float g_sj0[Nn * Tt];      // interleaved [n][t]
__device__ float g_sj1[Nn * Tt];
__device__ float g_rg[2][Tt * Tt];
__device__ float g_vg[2][Tt * Dd];
__device__ int   g_is64;

// ---- pre: dtype detect + zero deg/flags ----
__global__ void k_pre(const void* eidx) {
    int tid = threadIdx.x;            // 256, grid 64
    if (blockIdx.x == 0) {
        __shared__ int bad;
        if (tid == 0) bad = 0;
        __syncthreads();
        const long long* p = (const long long*)eidx;
        int b = 0;
#pragma unroll
        for (int k = 0; k < 4; k++) {
            long long v = p[tid + k * 256];
            if (v < 0 || v >= Nn) b = 1;
        }
        if (b) atomicExch(&bad, 1);
        __syncthreads();
        if (tid == 0) g_is64 = !bad;
        if (tid < 16) g_bflag[tid] = 0;
    }
    g_deg[blockIdx.x * 256 + tid] = 0;
}

// ---- hist: degree count; the returned rank makes scatter atomic-free ----
__global__ void k_hist(const void* __restrict__ eidx, const void* __restrict__ etyp) {
    int e = blockIdx.x * blockDim.x + threadIdx.x;
    if (e >= Ee) return;
    int r, c, t;
    if (g_is64) {
        r = (int)((const long long*)eidx)[e];
        c = (int)((const long long*)eidx)[Ee + e];
        t = (int)((const long long*)etyp)[e];
    } else {
        r = ((const int*)eidx)[e];
        c = ((const int*)eidx)[Ee + e];
        t = ((const int*)etyp)[e];
    }
    int rank = atomicAdd(&g_deg[r], 1);
    g_rr[e]  = r | (rank << 14);
    g_cet[e] = c | (t << 14);
}

// ---- single-kernel exclusive scan, 16 blocks, decoupled lookback ----
__global__ void k_scan() {
    __shared__ int sh[1024];
    __shared__ int base_s;
    int b = blockIdx.x, tid = threadIdx.x;
    int i = b * 1024 + tid;
    int v = g_deg[i];
    sh[tid] = v;
    __syncthreads();
    for (int off = 1; off < 1024; off <<= 1) {
        int u = (tid >= off) ? sh[tid - off] : 0;
        __syncthreads();
        sh[tid] += u;
        __syncthreads();
    }
    if (tid == 1023) {
        g_bval[b] = sh[1023];
        __threadfence();
        atomicExch(&g_bflag[b], 1);
    }
    if (tid == 0) {
        int acc = 0;
        for (int j = 0; j < b; j++) {
            while (atomicAdd(&g_bflag[j], 0) == 0) { }
            acc += g_bval[j];
        }
        base_s = acc;
    }
    __syncthreads();
    g_off[i] = sh[tid] - v + base_s;
    if (i == 0) g_off[Nn] = Ee;
}

// ---- scatter: atomic-free (rank precomputed in hist) ----
__global__ void k_scatter() {
    int i = blockIdx.x * blockDim.x + threadIdx.x;
#pragma unroll
    for (int k = 0; k < 2; k++) {
        int e = i * 2 + k;
        int v = g_rr[e];
        int r = v & 16383;
        int rank = ((unsigned)v) >> 14;
        g_ect[g_off[r] + rank] = g_cet[e];
    }
}

// ---- rgef for BOTH layers (one block) ----
__device__ void rgef_body(const float* __restrict__ ef0, const float* __restrict__ theta,
                          const float* __restrict__ wr) {
    __shared__ float efa[Tt * Dd], efb[Tt * Dd];
    int tid = threadIdx.x;              // 256
    int t = tid >> 6, d = tid & 63;
    efa[tid] = ef0[tid];
    __syncthreads();
    if (tid < Tt * Tt) {
        int t1 = tid >> 2, t2 = tid & 3;
        const float* tg = theta + t1 * 3 * Dd;
        float s = 0.f;
#pragma unroll
        for (int k = 0; k < Dd; k++) s += tg[k] * efa[t2 * Dd + k];
        g_rg[0][tid] = s;
    }
    {
        float s = 0.f;
#pragma unroll
        for (int k = 0; k < Dd; k++) s += efa[t * Dd + k] * wr[k * Dd + d];
        g_vg[0][tid] = 1.f / (1.f + __expf(-s));
        efb[tid] = fmaxf(s, 0.f);
    }
    __syncthreads();
    if (tid < Tt * Tt) {
        int t1 = tid >> 2, t2 = tid & 3;
        const float* tg = theta + (Tt * 3 * Dd) + t1 * 3 * Dd;
        float s = 0.f;
#pragma unroll
        for (int k = 0; k < Dd; k++) s += tg[k] * efb[t2 * Dd + k];
        g_rg[1][tid] = s;
    }
    {
        const float* w1 = wr + Dd * Dd;
        float s = 0.f;
#pragma unroll
        for (int k = 0; k < Dd; k++) s += efb[t * Dd + k] * w1[k * Dd + d];
        g_vg[1][tid] = 1.f / (1.f + __expf(-s));
    }
}

// ---- layer-0 gemm: hw0 = x @ we0 + sj0 for all 4 t + rgef both layers ----
__global__ void k_gemm0(const float* __restrict__ x, const float* __restrict__ ef0,
                        const float* __restrict__ we, const float* __restrict__ theta,
                        const float* __restrict__ wr) {
    if (blockIdx.x == Nn / 32) { rgef_body(ef0, theta, wr); return; }
    __shared__ float we_s[Dd * Dd];
    __shared__ float h_s[32 * Dd];
    __shared__ float thj_s[Tt * Dd];
    int tid = threadIdx.x;              // 256
    int n0 = blockIdx.x * 32;
#pragma unroll
    for (int i = 0; i < 16; i++) we_s[tid + i * 256] = we[tid + i * 256];
    const float* hb = x + (size_t)n0 * Dd;
#pragma unroll
    for (int i = 0; i < 8; i++) h_s[tid + i * 256] = hb[tid + i * 256];
    {
        int t = tid >> 6, d = tid & 63;
        thj_s[t * Dd + d] = theta[t * 3 * Dd + 2 * Dd + d];
    }
    __syncthreads();
    int d = tid & 63, ng = tid >> 6;
    float acc[8] = {0.f, 0.f, 0.f, 0.f, 0.f, 0.f, 0.f, 0.f};
#pragma unroll
    for (int k = 0; k < Dd; k++) {
        float wv = we_s[k * Dd + d];
#pragma unroll
        for (int j = 0; j < 8; j++) acc[j] += h_s[(ng * 8 + j) * Dd + k] * wv;
    }
    float* ob = g_hw0 + (size_t)n0 * Dd;
#pragma unroll
    for (int j = 0; j < 8; j++) ob[(ng * 8 + j) * Dd + d] = acc[j];

    int wid = tid >> 5, lane = tid & 31;
#pragma unroll
    for (int j = 0; j < 4; j++) {
        int nl = wid * 4 + j;
        float a = h_s[nl * Dd + lane], b = h_s[nl * Dd + lane + 32];
#pragma unroll
        for (int t = 0; t < Tt; t++) {
            float sj = a * thj_s[t * Dd + lane] + b * thj_s[t * Dd + lane + 32];
#pragma unroll
            for (int o = 16; o; o >>= 1) sj += __shfl_down_sync(0xffffffffu, sj, o);
            if (lane == 0) g_sj0[(n0 + nl) * Tt + t] = sj;
        }
    }
}

// ---- fused layer 0: warp per NODE, raw exp (softmax is shift-invariant, logits tiny),
//      per-lane denominators reduced once at the end; epilogue produces hw1 + sj1 ----
__global__ void k_fused0(const float* __restrict__ theta, const float* __restrict__ we) {
    __shared__ float vg_s[Tt * Dd];
    __shared__ float rg_s[Tt * Tt];
    __shared__ float we1_s[Dd * Dd];
    __shared__ float thj1_s[Tt * Dd];
    __shared__ float4 p4_s[8][32];
    __shared__ int   pk_s[8][32];
    __shared__ float h_s[8][Dd];
    int tid = threadIdx.x;              // 256 = 8 warps = 8 nodes
    vg_s[tid] = g_vg[0][tid];
    if (tid < Tt * Tt) rg_s[tid] = g_rg[0][tid];
    const float* w1 = we + Dd * Dd;
#pragma unroll
    for (int i = 0; i < 16; i++) we1_s[tid + i * 256] = w1[tid + i * 256];
    {
        int t = tid >> 6, d = tid & 63;
        thj1_s[t * Dd + d] = theta[(Tt * 3 * Dd) + t * 3 * Dd + 2 * Dd + d];
    }
    __syncthreads();
    int w = tid >> 5, lane = tid & 31;
    int n = blockIdx.x * 8 + w;
    int beg = g_off[n], end = g_off[n + 1];
    const float4* sj4p = (const float4*)g_sj0;
    float a0l = 0.f, a0h = 0.f, a1l = 0.f, a1h = 0.f;
    float a2l = 0.f, a2h = 0.f, a3l = 0.f, a3h = 0.f;
    float s0 = 0.f, s1 = 0.f, s2 = 0.f, s3 = 0.f;   // per-lane partials

    for (int base = beg; base < end; base += 32) {
        int cnt = min(32, end - base);
        float p0 = 0.f, p1 = 0.f, p2 = 0.f, p3 = 0.f;
        int pk = 0;
        if (lane < cnt) {
            pk = g_ect[base + lane];
            float4 sj4 = sj4p[pk & 16383];
            const float* rgc = rg_s + (pk >> 14);
            p0 = __expf(rgc[0]  + sj4.x);
            p1 = __expf(rgc[4]  + sj4.y);
            p2 = __expf(rgc[8]  + sj4.z);
            p3 = __expf(rgc[12] + sj4.w);
        }
        s0 += p0; s1 += p1; s2 += p2; s3 += p3;
        p4_s[w][lane] = make_float4(p0, p1, p2, p3);
        pk_s[w][lane] = pk;
        __syncwarp();
#pragma unroll 4
        for (int i = 0; i < cnt; i++) {
            float4 p = p4_s[w][i];
            int pki = pk_s[w][i];
            int ci = pki & 16383, tyi = pki >> 14;
            const float* hp = g_hw0 + (size_t)ci * Dd;
            float vl = vg_s[tyi * Dd + lane]      * hp[lane];
            float vh = vg_s[tyi * Dd + 32 + lane] * hp[lane + 32];
            a0l += p.x * vl; a0h += p.x * vh;
            a1l += p.y * vl; a1h += p.y * vh;
            a2l += p.z * vl; a2h += p.z * vh;
            a3l += p.w * vl; a3h += p.w * vh;
        }
        __syncwarp();
    }
#pragma unroll
    for (int o = 16; o; o >>= 1) {
        s0 += __shfl_xor_sync(0xffffffffu, s0, o);
        s1 += __shfl_xor_sync(0xffffffffu, s1, o);
        s2 += __shfl_xor_sync(0xffffffffu, s2, o);
        s3 += __shfl_xor_sync(0xffffffffu, s3, o);
    }

    float accl[Tt] = {a0l, a1l, a2l, a3l};
    float acch[Tt] = {a0h, a1h, a2h, a3h};
    float ss[Tt] = {s0, s1, s2, s3};
#pragma unroll
    for (int t = 0; t < Tt; t++) {
        float inv = ss[t] > 0.f ? 1.f / ss[t] : 0.f;
        float v0 = fmaxf(accl[t] * inv, 0.f);
        float v1 = fmaxf(acch[t] * inv, 0.f);
        h_s[w][lane] = v0; h_s[w][lane + 32] = v1;
        __syncwarp();
        float o0 = 0.f, o1 = 0.f;
#pragma unroll
        for (int k = 0; k < Dd; k++) {
            float hv = h_s[w][k];
            o0 += hv * we1_s[k * Dd + lane];
            o1 += hv * we1_s[k * Dd + lane + 32];
        }
        size_t ob = (size_t)t * (Nn * Dd) + (size_t)n * Dd;
        g_hw1[ob + lane] = o0;
        g_hw1[ob + 32 + lane] = o1;
        float sj = v0 * thj1_s[t * Dd + lane] + v1 * thj1_s[t * Dd + lane + 32];
#pragma unroll
        for (int o = 16; o; o >>= 1) sj += __shfl_down_sync(0xffffffffu, sj, o);
        if (lane == 0) g_sj1[n * Tt + t] = sj;
        __syncwarp();
    }
}

// ---- fused layer 1: warp per (node, type), raw exp, per-lane denominators ----
__global__ void k_fused1(float* __restrict__ out) {
    __shared__ float vg_s[Tt * Dd];
    __shared__ float rg_s[Tt * Tt];
    __shared__ uint2 spp[8][32];
    int tid = threadIdx.x;              // 256 = 2 nodes x 4 types
    vg_s[tid] = g_vg[1][tid];
    if (tid < Tt * Tt) rg_s[tid] = g_rg[1][tid];
    __syncthreads();
    int w = tid >> 5, lane = tid & 31;
    int n = blockIdx.x * 2 + (w >> 2);
    int t = w & 3;
    int beg = g_off[n], end = g_off[n + 1];
    const float* hwt = g_hw1 + (size_t)t * (Nn * Dd);
    const float* rgt = rg_s + t * 4;
    uint2* myspp = spp[w];
    float acc0 = 0.f, acc1 = 0.f, s = 0.f;

    for (int base = beg; base < end; base += 32) {
        int cnt = min(32, end - base);
        float p = 0.f;
        int pk = 0;
        if (lane < cnt) {
            pk = g_ect[base + lane];
            p = __expf(rgt[pk >> 14] + g_sj1[(pk & 16383) * Tt + t]);
        }
        s += p;
        myspp[lane] = make_uint2(__float_as_uint(p), (unsigned)pk);
        __syncwarp();
#pragma unroll 4
        for (int i = 0; i < cnt; i++) {
            uint2 q = myspp[i];
            float pi = __uint_as_float(q.x);
            int ci = q.y & 16383, tyi = q.y >> 14;
            const float* hp = hwt + (size_t)ci * Dd;
            acc0 += pi * vg_s[tyi * Dd + lane]      * hp[lane];
            acc1 += pi * vg_s[tyi * Dd + 32 + lane] * hp[lane + 32];
        }
        __syncwarp();
    }
#pragma unroll
    for (int o = 16; o; o >>= 1) s += __shfl_xor_sync(0xffffffffu, s, o);

    float inv = s > 0.f ? 1.f / s : 0.f;
    size_t ob = (size_t)t * (Nn * Dd) + (size_t)n * Dd;
    out[ob + lane]      = acc0 * inv;
    out[ob + 32 + lane] = acc1 * inv;
}

extern "C" void kernel_launch(void* const* d_in, const int* in_sizes, int n_in,
                              void* d_out, int out_size) {
    const float* x     = (const float*)d_in[0];
    const float* ef0   = (const float*)d_in[1];
    const float* theta = (const float*)d_in[2];
    const float* wr    = (const float*)d_in[3];
    const float* we    = (const float*)d_in[4];
    const void*  eidx  = d_in[5];
    const void*  etyp  = d_in[6];
    float* out = (float*)d_out;

    k_pre<<<64, 256>>>(eidx);
    k_hist<<<Ee / 256, 256>>>(eidx, etyp);
    k_scan<<<16, 1024>>>();
    k_scatter<<<Ee / 512, 256>>>();
    k_gemm0<<<Nn / 32 + 1, 256>>>(x, ef0, we, theta, wr);
    k_fused0<<<Nn / 8, 256>>>(theta, we);
    k_fused1<<<Nn / 2, 256>>>(out);
}

// round 8
// speedup vs baseline: 1.6697x; 1.0202x over previous
#include <cuda_runtime.h>
#include <math.h>

#define Nn 16384
#define Ee 262144
#define Tt 4
#define Dd 64
#define TND (Tt*Nn*Dd)

// ---- scratch ----
__device__ int   g_rr[Ee];            // packed (row | rank<<14)
__device__ int   g_cet[Ee];           // raw packed (col | ty<<14)
__device__ int   g_ect[Ee];           // CSR-sorted packed
__device__ int   g_deg[Nn], g_off[Nn + 1];
__device__ int   g_bval[16], g_bflag[16];
__device__ float g_hw0[Nn * Dd];      // x @ we0 (single plane)
__device__ float g_hw1[TND];          // h1 @ we1, INTERLEAVED [n][t][d]
__device__ float g_sj0[Nn * Tt];      // interleaved [n][t]
__device__ float g_sj1[Nn * Tt];
__device__ float g_rg[2][Tt * Tt];
__device__ float g_vg[2][Tt * Dd];
__device__ int   g_is64;

// ---- pre: dtype detect + zero deg/flags ----
__global__ void k_pre(const void* eidx) {
    int tid = threadIdx.x;            // 256, grid 64
    if (blockIdx.x == 0) {
        __shared__ int bad;
        if (tid == 0) bad = 0;
        __syncthreads();
        const long long* p = (const long long*)eidx;
        int b = 0;
#pragma unroll
        for (int k = 0; k < 4; k++) {
            long long v = p[tid + k * 256];
            if (v < 0 || v >= Nn) b = 1;
        }
        if (b) atomicExch(&bad, 1);
        __syncthreads();
        if (tid == 0) g_is64 = !bad;
        if (tid < 16) g_bflag[tid] = 0;
    }
    g_deg[blockIdx.x * 256 + tid] = 0;
}

// ---- hist: degree count; returned rank makes scatter atomic-free ----
__global__ void k_hist(const void* __restrict__ eidx, const void* __restrict__ etyp) {
    int e = blockIdx.x * blockDim.x + threadIdx.x;
    if (e >= Ee) return;
    int r, c, t;
    if (g_is64) {
        r = (int)((const long long*)eidx)[e];
        c = (int)((const long long*)eidx)[Ee + e];
        t = (int)((const long long*)etyp)[e];
    } else {
        r = ((const int*)eidx)[e];
        c = ((const int*)eidx)[Ee + e];
        t = ((const int*)etyp)[e];
    }
    int rank = atomicAdd(&g_deg[r], 1);
    g_rr[e]  = r | (rank << 14);
    g_cet[e] = c | (t << 14);
}

// ---- single-kernel exclusive scan, 16 blocks, decoupled lookback ----
__global__ void k_scan() {
    __shared__ int sh[1024];
    __shared__ int base_s;
    int b = blockIdx.x, tid = threadIdx.x;
    int i = b * 1024 + tid;
    int v = g_deg[i];
    sh[tid] = v;
    __syncthreads();
    for (int off = 1; off < 1024; off <<= 1) {
        int u = (tid >= off) ? sh[tid - off] : 0;
        __syncthreads();
        sh[tid] += u;
        __syncthreads();
    }
    if (tid == 1023) {
        g_bval[b] = sh[1023];
        __threadfence();
        atomicExch(&g_bflag[b], 1);
    }
    if (tid == 0) {
        int acc = 0;
        for (int j = 0; j < b; j++) {
            while (atomicAdd(&g_bflag[j], 0) == 0) { }
            acc += g_bval[j];
        }
        base_s = acc;
    }
    __syncthreads();
    g_off[i] = sh[tid] - v + base_s;
    if (i == 0) g_off[Nn] = Ee;
}

// ---- scatter: atomic-free ----
__global__ void k_scatter() {
    int i = blockIdx.x * blockDim.x + threadIdx.x;
#pragma unroll
    for (int k = 0; k < 2; k++) {
        int e = i * 2 + k;
        int v = g_rr[e];
        int r = v & 16383;
        int rank = ((unsigned)v) >> 14;
        g_ect[g_off[r] + rank] = g_cet[e];
    }
}

// ---- rgef for BOTH layers ----
__device__ void rgef_body(const float* __restrict__ ef0, const float* __restrict__ theta,
                          const float* __restrict__ wr) {
    __shared__ float efa[Tt * Dd], efb[Tt * Dd];
    int tid = threadIdx.x;              // 256
    int t = tid >> 6, d = tid & 63;
    efa[tid] = ef0[tid];
    __syncthreads();
    if (tid < Tt * Tt) {
        int t1 = tid >> 2, t2 = tid & 3;
        const float* tg = theta + t1 * 3 * Dd;
        float s = 0.f;
#pragma unroll
        for (int k = 0; k < Dd; k++) s += tg[k] * efa[t2 * Dd + k];
        g_rg[0][tid] = s;
    }
    {
        float s = 0.f;
#pragma unroll
        for (int k = 0; k < Dd; k++) s += efa[t * Dd + k] * wr[k * Dd + d];
        g_vg[0][tid] = 1.f / (1.f + __expf(-s));
        efb[tid] = fmaxf(s, 0.f);
    }
    __syncthreads();
    if (tid < Tt * Tt) {
        int t1 = tid >> 2, t2 = tid & 3;
        const float* tg = theta + (Tt * 3 * Dd) + t1 * 3 * Dd;
        float s = 0.f;
#pragma unroll
        for (int k = 0; k < Dd; k++) s += tg[k] * efb[t2 * Dd + k];
        g_rg[1][tid] = s;
    }
    {
        const float* w1 = wr + Dd * Dd;
        float s = 0.f;
#pragma unroll
        for (int k = 0; k < Dd; k++) s += efb[t * Dd + k] * w1[k * Dd + d];
        g_vg[1][tid] = 1.f / (1.f + __expf(-s));
    }
}

// ---- layer-0 gemm: hw0 = x @ we0 + sj0 + rgef ----
__global__ void k_gemm0(const float* __restrict__ x, const float* __restrict__ ef0,
                        const float* __restrict__ we, const float* __restrict__ theta,
                        const float* __restrict__ wr) {
    if (blockIdx.x == Nn / 32) { rgef_body(ef0, theta, wr); return; }
    __shared__ float we_s[Dd * Dd];
    __shared__ float h_s[32 * Dd];
    __shared__ float thj_s[Tt * Dd];
    int tid = threadIdx.x;              // 256
    int n0 = blockIdx.x * 32;
#pragma unroll
    for (int i = 0; i < 16; i++) we_s[tid + i * 256] = we[tid + i * 256];
    const float* hb = x + (size_t)n0 * Dd;
#pragma unroll
    for (int i = 0; i < 8; i++) h_s[tid + i * 256] = hb[tid + i * 256];
    {
        int t = tid >> 6, d = tid & 63;
        thj_s[t * Dd + d] = theta[t * 3 * Dd + 2 * Dd + d];
    }
    __syncthreads();
    int d = tid & 63, ng = tid >> 6;
    float acc[8] = {0.f, 0.f, 0.f, 0.f, 0.f, 0.f, 0.f, 0.f};
#pragma unroll
    for (int k = 0; k < Dd; k++) {
        float wv = we_s[k * Dd + d];
#pragma unroll
        for (int j = 0; j < 8; j++) acc[j] += h_s[(ng * 8 + j) * Dd + k] * wv;
    }
    float* ob = g_hw0 + (size_t)n0 * Dd;
#pragma unroll
    for (int j = 0; j < 8; j++) ob[(ng * 8 + j) * Dd + d] = acc[j];

    int wid = tid >> 5, lane = tid & 31;
#pragma unroll
    for (int j = 0; j < 4; j++) {
        int nl = wid * 4 + j;
        float a = h_s[nl * Dd + lane], b = h_s[nl * Dd + lane + 32];
#pragma unroll
        for (int t = 0; t < Tt; t++) {
            float sj = a * thj_s[t * Dd + lane] + b * thj_s[t * Dd + lane + 32];
#pragma unroll
            for (int o = 16; o; o >>= 1) sj += __shfl_down_sync(0xffffffffu, sj, o);
            if (lane == 0) g_sj0[(n0 + nl) * Tt + t] = sj;
        }
    }
}

// ---- fused layer 0: warp per NODE; epilogue writes INTERLEAVED hw1 + sj1 ----
__global__ void k_fused0(const float* __restrict__ theta, const float* __restrict__ we) {
    __shared__ float vg_s[Tt * Dd];
    __shared__ float rg_s[Tt * Tt];
    __shared__ float we1_s[Dd * Dd];
    __shared__ float thj1_s[Tt * Dd];
    __shared__ float4 p4_s[8][32];
    __shared__ int   pk_s[8][32];
    __shared__ float h_s[8][Dd];
    int tid = threadIdx.x;              // 256 = 8 warps = 8 nodes
    vg_s[tid] = g_vg[0][tid];
    if (tid < Tt * Tt) rg_s[tid] = g_rg[0][tid];
    const float* w1 = we + Dd * Dd;
#pragma unroll
    for (int i = 0; i < 16; i++) we1_s[tid + i * 256] = w1[tid + i * 256];
    {
        int t = tid >> 6, d = tid & 63;
        thj1_s[t * Dd + d] = theta[(Tt * 3 * Dd) + t * 3 * Dd + 2 * Dd + d];
    }
    __syncthreads();
    int w = tid >> 5, lane = tid & 31;
    int n = blockIdx.x * 8 + w;
    int beg = g_off[n], end = g_off[n + 1];
    const float4* sj4p = (const float4*)g_sj0;
    float a0l = 0.f, a0h = 0.f, a1l = 0.f, a1h = 0.f;
    float a2l = 0.f, a2h = 0.f, a3l = 0.f, a3h = 0.f;
    float s0 = 0.f, s1 = 0.f, s2 = 0.f, s3 = 0.f;

    for (int base = beg; base < end; base += 32) {
        int cnt = min(32, end - base);
        float p0 = 0.f, p1 = 0.f, p2 = 0.f, p3 = 0.f;
        int pk = 0;
        if (lane < cnt) {
            pk = g_ect[base + lane];
            float4 sj4 = sj4p[pk & 16383];
            const float* rgc = rg_s + (pk >> 14);
            p0 = __expf(rgc[0]  + sj4.x);
            p1 = __expf(rgc[4]  + sj4.y);
            p2 = __expf(rgc[8]  + sj4.z);
            p3 = __expf(rgc[12] + sj4.w);
        }
        s0 += p0; s1 += p1; s2 += p2; s3 += p3;
        p4_s[w][lane] = make_float4(p0, p1, p2, p3);
        pk_s[w][lane] = pk;
        __syncwarp();
#pragma unroll 4
        for (int i = 0; i < cnt; i++) {
            float4 p = p4_s[w][i];
            int pki = pk_s[w][i];
            int ci = pki & 16383, tyi = pki >> 14;
            const float* hp = g_hw0 + (size_t)ci * Dd;
            float vl = vg_s[tyi * Dd + lane]      * hp[lane];
            float vh = vg_s[tyi * Dd + 32 + lane] * hp[lane + 32];
            a0l += p.x * vl; a0h += p.x * vh;
            a1l += p.y * vl; a1h += p.y * vh;
            a2l += p.z * vl; a2h += p.z * vh;
            a3l += p.w * vl; a3h += p.w * vh;
        }
        __syncwarp();
    }
#pragma unroll
    for (int o = 16; o; o >>= 1) {
        s0 += __shfl_xor_sync(0xffffffffu, s0, o);
        s1 += __shfl_xor_sync(0xffffffffu, s1, o);
        s2 += __shfl_xor_sync(0xffffffffu, s2, o);
        s3 += __shfl_xor_sync(0xffffffffu, s3, o);
    }

    float accl[Tt] = {a0l, a1l, a2l, a3l};
    float acch[Tt] = {a0h, a1h, a2h, a3h};
    float ss[Tt] = {s0, s1, s2, s3};
#pragma unroll
    for (int t = 0; t < Tt; t++) {
        float inv = ss[t] > 0.f ? 1.f / ss[t] : 0.f;
        float v0 = fmaxf(accl[t] * inv, 0.f);
        float v1 = fmaxf(acch[t] * inv, 0.f);
        h_s[w][lane] = v0; h_s[w][lane + 32] = v1;
        __syncwarp();
        float o0 = 0.f, o1 = 0.f;
#pragma unroll
        for (int k = 0; k < Dd; k++) {
            float hv = h_s[w][k];
            o0 += hv * we1_s[k * Dd + lane];
            o1 += hv * we1_s[k * Dd + lane + 32];
        }
        size_t ob = (size_t)n * (Tt * Dd) + (size_t)t * Dd;   // interleaved [n][t][d]
        g_hw1[ob + lane] = o0;
        g_hw1[ob + 32 + lane] = o1;
        float sj = v0 * thj1_s[t * Dd + lane] + v1 * thj1_s[t * Dd + lane + 32];
#pragma unroll
        for (int o = 16; o; o >>= 1) sj += __shfl_down_sync(0xffffffffu, sj, o);
        if (lane == 0) g_sj1[n * Tt + t] = sj;
        __syncwarp();
    }
}

// ---- fused layer 1: warp per NODE, contiguous 1KB hw1 gather per edge ----
__global__ void k_fused1(float* __restrict__ out) {
    __shared__ float vg_s[Tt * Dd];
    __shared__ float rg_s[Tt * Tt];
    __shared__ float4 p4_s[8][32];
    __shared__ int   pk_s[8][32];
    int tid = threadIdx.x;              // 256 = 8 warps = 8 nodes
    vg_s[tid] = g_vg[1][tid];
    if (tid < Tt * Tt) rg_s[tid] = g_rg[1][tid];
    __syncthreads();
    int w = tid >> 5, lane = tid & 31;
    int n = blockIdx.x * 8 + w;
    int beg = g_off[n], end = g_off[n + 1];
    const float4* sj4p = (const float4*)g_sj1;
    float a0l = 0.f, a0h = 0.f, a1l = 0.f, a1h = 0.f;
    float a2l = 0.f, a2h = 0.f, a3l = 0.f, a3h = 0.f;
    float s0 = 0.f, s1 = 0.f, s2 = 0.f, s3 = 0.f;

    for (int base = beg; base < end; base += 32) {
        int cnt = min(32, end - base);
        float p0 = 0.f, p1 = 0.f, p2 = 0.f, p3 = 0.f;
        int pk = 0;
        if (lane < cnt) {
            pk = g_ect[base + lane];
            float4 sj4 = sj4p[pk & 16383];
            const float* rgc = rg_s + (pk >> 14);
            p0 = __expf(rgc[0]  + sj4.x);
            p1 = __expf(rgc[4]  + sj4.y);
            p2 = __expf(rgc[8]  + sj4.z);
            p3 = __expf(rgc[12] + sj4.w);
        }
        s0 += p0; s1 += p1; s2 += p2; s3 += p3;
        p4_s[w][lane] = make_float4(p0, p1, p2, p3);
        pk_s[w][lane] = pk;
        __syncwarp();
#pragma unroll 2
        for (int i = 0; i < cnt; i++) {
            float4 p = p4_s[w][i];
            int pki = pk_s[w][i];
            int ci = pki & 16383, tyi = pki >> 14;
            const float* hp = g_hw1 + (size_t)ci * (Tt * Dd);
            float vl = vg_s[tyi * Dd + lane];
            float vh = vg_s[tyi * Dd + 32 + lane];
            a0l += p.x * vl * hp[lane];           a0h += p.x * vh * hp[lane + 32];
            a1l += p.y * vl * hp[Dd + lane];      a1h += p.y * vh * hp[Dd + lane + 32];
            a2l += p.z * vl * hp[2 * Dd + lane];  a2h += p.z * vh * hp[2 * Dd + lane + 32];
            a3l += p.w * vl * hp[3 * Dd + lane];  a3h += p.w * vh * hp[3 * Dd + lane + 32];
        }
        __syncwarp();
    }
#pragma unroll
    for (int o = 16; o; o >>= 1) {
        s0 += __shfl_xor_sync(0xffffffffu, s0, o);
        s1 += __shfl_xor_sync(0xffffffffu, s1, o);
        s2 += __shfl_xor_sync(0xffffffffu, s2, o);
        s3 += __shfl_xor_sync(0xffffffffu, s3, o);
    }
    float accl[Tt] = {a0l, a1l, a2l, a3l};
    float acch[Tt] = {a0h, a1h, a2h, a3h};
    float ss[Tt] = {s0, s1, s2, s3};
#pragma unroll
    for (int t = 0; t < Tt; t++) {
        float inv = ss[t] > 0.f ? 1.f / ss[t] : 0.f;
        size_t ob = (size_t)t * (Nn * Dd) + (size_t)n * Dd;   // output stays (T,N,D)
        out[ob + lane]      = accl[t] * inv;
        out[ob + 32 + lane] = acch[t] * inv;
    }
}

extern "C" void kernel_launch(void* const* d_in, const int* in_sizes, int n_in,
                              void* d_out, int out_size) {
    const float* x     = (const float*)d_in[0];
    const float* ef0   = (const float*)d_in[1];
    const float* theta = (const float*)d_in[2];
    const float* wr    = (const float*)d_in[3];
    const float* we    = (const float*)d_in[4];
    const void*  eidx  = d_in[5];
    const void*  etyp  = d_in[6];
    float* out = (float*)d_out;

    k_pre<<<64, 256>>>(eidx);
    k_hist<<<Ee / 256, 256>>>(eidx, etyp);
    k_scan<<<16, 1024>>>();
    k_scatter<<<Ee / 512, 256>>>();
    k_gemm0<<<Nn / 32 + 1, 256>>>(x, ef0, we, theta, wr);
    k_fused0<<<Nn / 8, 256>>>(theta, we);
    k_fused1<<<Nn / 8, 256>>>(out);
}

// round 9
// speedup vs baseline: 1.8354x; 1.0992x over previous
#include <cuda_runtime.h>
#include <math.h>

#define Nn 16384
#define Ee 262144
#define Tt 4
#define Dd 64
#define TND (Tt*Nn*Dd)

// ---- scratch ----
__device__ int   g_rr[Ee];            // packed (row | rank<<14)
__device__ int   g_cet[Ee];           // raw packed (col | ty<<14)
__device__ int   g_ect[Ee];           // CSR-sorted packed
__device__ int   g_deg[Nn], g_off[Nn + 1];
__device__ int   g_bval[16], g_bflag[16];
__device__ float g_hw0[Nn * Dd];      // x @ we0 (single plane)
__device__ float g_hw1[TND];          // h1 @ we1, INTERLEAVED [n][t][d]
__device__ float g_sj0[Nn * Tt];      // interleaved [n][t]
__device__ float g_sj1[Nn * Tt];
__device__ float g_rg[2][Tt * Tt];
__device__ float g_vg[2][Tt * Dd];
__device__ int   g_is64;

// ---- pre: dtype detect + zero deg/flags ----
__global__ void k_pre(const void* eidx) {
    int tid = threadIdx.x;            // 256, grid 64
    if (blockIdx.x == 0) {
        __shared__ int bad;
        if (tid == 0) bad = 0;
        __syncthreads();
        const long long* p = (const long long*)eidx;
        int b = 0;
#pragma unroll
        for (int k = 0; k < 4; k++) {
            long long v = p[tid + k * 256];
            if (v < 0 || v >= Nn) b = 1;
        }
        if (b) atomicExch(&bad, 1);
        __syncthreads();
        if (tid == 0) g_is64 = !bad;
        if (tid < 16) g_bflag[tid] = 0;
    }
    g_deg[blockIdx.x * 256 + tid] = 0;
}

// ---- hist: degree count; returned rank makes scatter atomic-free ----
__global__ void k_hist(const void* __restrict__ eidx, const void* __restrict__ etyp) {
    int e = blockIdx.x * blockDim.x + threadIdx.x;
    if (e >= Ee) return;
    int r, c, t;
    if (g_is64) {
        r = (int)((const long long*)eidx)[e];
        c = (int)((const long long*)eidx)[Ee + e];
        t = (int)((const long long*)etyp)[e];
    } else {
        r = ((const int*)eidx)[e];
        c = ((const int*)eidx)[Ee + e];
        t = ((const int*)etyp)[e];
    }
    int rank = atomicAdd(&g_deg[r], 1);
    g_rr[e]  = r | (rank << 14);
    g_cet[e] = c | (t << 14);
}

// ---- single-kernel exclusive scan, 16 blocks, decoupled lookback ----
__global__ void k_scan() {
    __shared__ int sh[1024];
    __shared__ int base_s;
    int b = blockIdx.x, tid = threadIdx.x;
    int i = b * 1024 + tid;
    int v = g_deg[i];
    sh[tid] = v;
    __syncthreads();
    for (int off = 1; off < 1024; off <<= 1) {
        int u = (tid >= off) ? sh[tid - off] : 0;
        __syncthreads();
        sh[tid] += u;
        __syncthreads();
    }
    if (tid == 1023) {
        g_bval[b] = sh[1023];
        __threadfence();
        atomicExch(&g_bflag[b], 1);
    }
    if (tid == 0) {
        int acc = 0;
        for (int j = 0; j < b; j++) {
            while (atomicAdd(&g_bflag[j], 0) == 0) { }
            acc += g_bval[j];
        }
        base_s = acc;
    }
    __syncthreads();
    g_off[i] = sh[tid] - v + base_s;
    if (i == 0) g_off[Nn] = Ee;
}

// ---- scatter: atomic-free, 4 edges/thread, batched wide loads ----
__global__ void k_scatter() {
    int i = blockIdx.x * blockDim.x + threadIdx.x;
    int4 rr = ((const int4*)g_rr)[i];
    int4 ce = ((const int4*)g_cet)[i];
    int p0 = g_off[rr.x & 16383] + (((unsigned)rr.x) >> 14);
    int p1 = g_off[rr.y & 16383] + (((unsigned)rr.y) >> 14);
    int p2 = g_off[rr.z & 16383] + (((unsigned)rr.z) >> 14);
    int p3 = g_off[rr.w & 16383] + (((unsigned)rr.w) >> 14);
    g_ect[p0] = ce.x;
    g_ect[p1] = ce.y;
    g_ect[p2] = ce.z;
    g_ect[p3] = ce.w;
}

// ---- rgef for BOTH layers ----
__device__ void rgef_body(const float* __restrict__ ef0, const float* __restrict__ theta,
                          const float* __restrict__ wr) {
    __shared__ float efa[Tt * Dd], efb[Tt * Dd];
    int tid = threadIdx.x;              // 256
    int t = tid >> 6, d = tid & 63;
    efa[tid] = ef0[tid];
    __syncthreads();
    if (tid < Tt * Tt) {
        int t1 = tid >> 2, t2 = tid & 3;
        const float* tg = theta + t1 * 3 * Dd;
        float s = 0.f;
#pragma unroll
        for (int k = 0; k < Dd; k++) s += tg[k] * efa[t2 * Dd + k];
        g_rg[0][tid] = s;
    }
    {
        float s = 0.f;
#pragma unroll
        for (int k = 0; k < Dd; k++) s += efa[t * Dd + k] * wr[k * Dd + d];
        g_vg[0][tid] = 1.f / (1.f + __expf(-s));
        efb[tid] = fmaxf(s, 0.f);
    }
    __syncthreads();
    if (tid < Tt * Tt) {
        int t1 = tid >> 2, t2 = tid & 3;
        const float* tg = theta + (Tt * 3 * Dd) + t1 * 3 * Dd;
        float s = 0.f;
#pragma unroll
        for (int k = 0; k < Dd; k++) s += tg[k] * efb[t2 * Dd + k];
        g_rg[1][tid] = s;
    }
    {
        const float* w1 = wr + Dd * Dd;
        float s = 0.f;
#pragma unroll
        for (int k = 0; k < Dd; k++) s += efb[t * Dd + k] * w1[k * Dd + d];
        g_vg[1][tid] = 1.f / (1.f + __expf(-s));
    }
}

// ---- layer-0 gemm: hw0 = x @ we0 + sj0 + rgef ----
__global__ void k_gemm0(const float* __restrict__ x, const float* __restrict__ ef0,
                        const float* __restrict__ we, const float* __restrict__ theta,
                        const float* __restrict__ wr) {
    if (blockIdx.x == Nn / 32) { rgef_body(ef0, theta, wr); return; }
    __shared__ float we_s[Dd * Dd];
    __shared__ float h_s[32 * Dd];
    __shared__ float thj_s[Tt * Dd];
    int tid = threadIdx.x;              // 256
    int n0 = blockIdx.x * 32;
#pragma unroll
    for (int i = 0; i < 16; i++) we_s[tid + i * 256] = we[tid + i * 256];
    const float* hb = x + (size_t)n0 * Dd;
#pragma unroll
    for (int i = 0; i < 8; i++) h_s[tid + i * 256] = hb[tid + i * 256];
    {
        int t = tid >> 6, d = tid & 63;
        thj_s[t * Dd + d] = theta[t * 3 * Dd + 2 * Dd + d];
    }
    __syncthreads();
    int d = tid & 63, ng = tid >> 6;
    float acc[8] = {0.f, 0.f, 0.f, 0.f, 0.f, 0.f, 0.f, 0.f};
#pragma unroll
    for (int k = 0; k < Dd; k++) {
        float wv = we_s[k * Dd + d];
#pragma unroll
        for (int j = 0; j < 8; j++) acc[j] += h_s[(ng * 8 + j) * Dd + k] * wv;
    }
    float* ob = g_hw0 + (size_t)n0 * Dd;
#pragma unroll
    for (int j = 0; j < 8; j++) ob[(ng * 8 + j) * Dd + d] = acc[j];

    int wid = tid >> 5, lane = tid & 31;
#pragma unroll
    for (int j = 0; j < 4; j++) {
        int nl = wid * 4 + j;
        float a = h_s[nl * Dd + lane], b = h_s[nl * Dd + lane + 32];
#pragma unroll
        for (int t = 0; t < Tt; t++) {
            float sj = a * thj_s[t * Dd + lane] + b * thj_s[t * Dd + lane + 32];
#pragma unroll
            for (int o = 16; o; o >>= 1) sj += __shfl_down_sync(0xffffffffu, sj, o);
            if (lane == 0) g_sj0[(n0 + nl) * Tt + t] = sj;
        }
    }
}

// ---- fused layer 0: warp per NODE, float2 lanes, pk double-buffer ----
__global__ void k_fused0(const float* __restrict__ theta, const float* __restrict__ we) {
    __shared__ float2 vg2_s[Tt * 32];
    __shared__ float  rg_s[Tt * Tt];
    __shared__ float2 we1_2[Dd * 32];
    __shared__ float2 thj1_2[Tt * 32];
    __shared__ float4 p4_s[8][32];
    __shared__ int    pk_s[8][32];
    __shared__ float  h_s[8][Dd];
    int tid = threadIdx.x;              // 256 = 8 warps = 8 nodes
    if (tid < 128) vg2_s[tid] = ((const float2*)g_vg[0])[tid];
    else if (tid < 128 + 128) thj1_2[tid - 128] = make_float2(
        theta[(Tt * 3 * Dd) + ((tid - 128) >> 5) * 3 * Dd + 2 * Dd + ((tid - 128) & 31) * 2],
        theta[(Tt * 3 * Dd) + ((tid - 128) >> 5) * 3 * Dd + 2 * Dd + ((tid - 128) & 31) * 2 + 1]);
    if (tid < Tt * Tt) rg_s[tid] = g_rg[0][tid];
    const float2* w1 = (const float2*)(we + Dd * Dd);
#pragma unroll
    for (int i = 0; i < 8; i++) we1_2[tid + i * 256] = w1[tid + i * 256];
    __syncthreads();
    int w = tid >> 5, lane = tid & 31;
    int n = blockIdx.x * 8 + w;
    int beg = g_off[n], end = g_off[n + 1];
    const float4* sj4p = (const float4*)g_sj0;
    float2 a0 = make_float2(0.f, 0.f), a1 = a0, a2 = a0, a3 = a0;
    float s0 = 0.f, s1 = 0.f, s2 = 0.f, s3 = 0.f;

    int pkbuf = (beg + lane < end) ? g_ect[beg + lane] : 0;
    for (int base = beg; base < end; base += 32) {
        int cnt = min(32, end - base);
        int pk = pkbuf;
        if (base + 32 + lane < end) pkbuf = g_ect[base + 32 + lane];  // prefetch next chunk
        float p0 = 0.f, p1 = 0.f, p2 = 0.f, p3 = 0.f;
        if (lane < cnt) {
            float4 sj4 = sj4p[pk & 16383];
            const float* rgc = rg_s + (pk >> 14);
            p0 = __expf(rgc[0]  + sj4.x);
            p1 = __expf(rgc[4]  + sj4.y);
            p2 = __expf(rgc[8]  + sj4.z);
            p3 = __expf(rgc[12] + sj4.w);
        }
        s0 += p0; s1 += p1; s2 += p2; s3 += p3;
        p4_s[w][lane] = make_float4(p0, p1, p2, p3);
        pk_s[w][lane] = pk;
        __syncwarp();
#pragma unroll 4
        for (int i = 0; i < cnt; i++) {
            float4 p = p4_s[w][i];
            int pki = pk_s[w][i];
            int ci = pki & 16383, tyi = pki >> 14;
            float2 h = ((const float2*)(g_hw0 + (size_t)ci * Dd))[lane];
            float2 v = vg2_s[tyi * 32 + lane];
            float vx = v.x * h.x, vy = v.y * h.y;
            a0.x += p.x * vx; a0.y += p.x * vy;
            a1.x += p.y * vx; a1.y += p.y * vy;
            a2.x += p.z * vx; a2.y += p.z * vy;
            a3.x += p.w * vx; a3.y += p.w * vy;
        }
        __syncwarp();
    }
#pragma unroll
    for (int o = 16; o; o >>= 1) {
        s0 += __shfl_xor_sync(0xffffffffu, s0, o);
        s1 += __shfl_xor_sync(0xffffffffu, s1, o);
        s2 += __shfl_xor_sync(0xffffffffu, s2, o);
        s3 += __shfl_xor_sync(0xffffffffu, s3, o);
    }

    float2 acc[Tt] = {a0, a1, a2, a3};
    float ss[Tt] = {s0, s1, s2, s3};
#pragma unroll
    for (int t = 0; t < Tt; t++) {
        float inv = ss[t] > 0.f ? 1.f / ss[t] : 0.f;
        float v0 = fmaxf(acc[t].x * inv, 0.f);
        float v1 = fmaxf(acc[t].y * inv, 0.f);
        h_s[w][2 * lane] = v0; h_s[w][2 * lane + 1] = v1;
        __syncwarp();
        float2 o2 = make_float2(0.f, 0.f);
#pragma unroll
        for (int k = 0; k < Dd; k++) {
            float hv = h_s[w][k];
            float2 wk = we1_2[k * 32 + lane];
            o2.x += hv * wk.x;
            o2.y += hv * wk.y;
        }
        ((float2*)(g_hw1 + (size_t)n * (Tt * Dd) + (size_t)t * Dd))[lane] = o2;
        float2 tj = thj1_2[t * 32 + lane];
        float sj = v0 * tj.x + v1 * tj.y;
#pragma unroll
        for (int o = 16; o; o >>= 1) sj += __shfl_down_sync(0xffffffffu, sj, o);
        if (lane == 0) g_sj1[n * Tt + t] = sj;
        __syncwarp();
    }
}

// ---- fused layer 1: warp per NODE, float2 lanes, contiguous 1KB gather ----
__global__ void k_fused1(float* __restrict__ out) {
    __shared__ float2 vg2_s[Tt * 32];
    __shared__ float  rg_s[Tt * Tt];
    __shared__ float4 p4_s[8][32];
    __shared__ int    pk_s[8][32];
    int tid = threadIdx.x;              // 256 = 8 warps = 8 nodes
    if (tid < 128) vg2_s[tid] = ((const float2*)g_vg[1])[tid];
    if (tid < Tt * Tt) rg_s[tid] = g_rg[1][tid];
    __syncthreads();
    int w = tid >> 5, lane = tid & 31;
    int n = blockIdx.x * 8 + w;
    int beg = g_off[n], end = g_off[n + 1];
    const float4* sj4p = (const float4*)g_sj1;
    float2 a0 = make_float2(0.f, 0.f), a1 = a0, a2 = a0, a3 = a0;
    float s0 = 0.f, s1 = 0.f, s2 = 0.f, s3 = 0.f;

    int pkbuf = (beg + lane < end) ? g_ect[beg + lane] : 0;
    for (int base = beg; base < end; base += 32) {
        int cnt = min(32, end - base);
        int pk = pkbuf;
        if (base + 32 + lane < end) pkbuf = g_ect[base + 32 + lane];
        float p0 = 0.f, p1 = 0.f, p2 = 0.f, p3 = 0.f;
        if (lane < cnt) {
            float4 sj4 = sj4p[pk & 16383];
            const float* rgc = rg_s + (pk >> 14);
            p0 = __expf(rgc[0]  + sj4.x);
            p1 = __expf(rgc[4]  + sj4.y);
            p2 = __expf(rgc[8]  + sj4.z);
            p3 = __expf(rgc[12] + sj4.w);
        }
        s0 += p0; s1 += p1; s2 += p2; s3 += p3;
        p4_s[w][lane] = make_float4(p0, p1, p2, p3);
        pk_s[w][lane] = pk;
        __syncwarp();
#pragma unroll 2
        for (int i = 0; i < cnt; i++) {
            float4 p = p4_s[w][i];
            int pki = pk_s[w][i];
            int ci = pki & 16383, tyi = pki >> 14;
            const float2* hp = (const float2*)(g_hw1 + (size_t)ci * (Tt * Dd));
            float2 v = vg2_s[tyi * 32 + lane];
            float2 h0 = hp[lane], h1 = hp[32 + lane], h2 = hp[64 + lane], h3 = hp[96 + lane];
            a0.x += p.x * v.x * h0.x; a0.y += p.x * v.y * h0.y;
            a1.x += p.y * v.x * h1.x; a1.y += p.y * v.y * h1.y;
            a2.x += p.z * v.x * h2.x; a2.y += p.z * v.y * h2.y;
            a3.x += p.w * v.x * h3.x; a3.y += p.w * v.y * h3.y;
        }
        __syncwarp();
    }
#pragma unroll
    for (int o = 16; o; o >>= 1) {
        s0 += __shfl_xor_sync(0xffffffffu, s0, o);
        s1 += __shfl_xor_sync(0xffffffffu, s1, o);
        s2 += __shfl_xor_sync(0xffffffffu, s2, o);
        s3 += __shfl_xor_sync(0xffffffffu, s3, o);
    }
    float2 acc[Tt] = {a0, a1, a2, a3};
    float ss[Tt] = {s0, s1, s2, s3};
#pragma unroll
    for (int t = 0; t < Tt; t++) {
        float inv = ss[t] > 0.f ? 1.f / ss[t] : 0.f;
        float2 o2 = make_float2(acc[t].x * inv, acc[t].y * inv);
        ((float2*)(out + (size_t)t * (Nn * Dd) + (size_t)n * Dd))[lane] = o2;
    }
}

extern "C" void kernel_launch(void* const* d_in, const int* in_sizes, int n_in,
                              void* d_out, int out_size) {
    const float* x     = (const float*)d_in[0];
    const float* ef0   = (const float*)d_in[1];
    const float* theta = (const float*)d_in[2];
    const float* wr    = (const float*)d_in[3];
    const float* we    = (const float*)d_in[4];
    const void*  eidx  = d_in[5];
    const void*  etyp  = d_in[6];
    float* out = (float*)d_out;

    k_pre<<<64, 256>>>(eidx);
    k_hist<<<Ee / 256, 256>>>(eidx, etyp);
    k_scan<<<16, 1024>>>();
    k_scatter<<<Ee / 1024, 256>>>();
    k_gemm0<<<Nn / 32 + 1, 256>>>(x, ef0, we, theta, wr);
    k_fused0<<<Nn / 8, 256>>>(theta, we);
    k_fused1<<<Nn / 8, 256>>>(out);
}